// round 5
// baseline (speedup 1.0000x reference)
#include <cuda_runtime.h>
#include <cuda_fp16.h>
#include <cstdint>

// ---------------------------------------------------------------------------
// y[b,o] = sum_i x[b,i] * lut[widx[o,i]] + bias[o]
//   B=32, IN=8192, OUT=16384 ; lut affine: lut[c] = lut[0] + c*(lut[1]-lut[0])
//
// Exact-precision fp16 MMA scheme (validated R3/R4):
//   A = (idx-128) exact in fp16 via (0x6400|idx) -> 1024+idx, HSUB2 1152.
//   x = x_hi + x_lo fp16 split; 2x mma.m16n8k16.f16, fp32 accum.
//   y = sc*acc + c0*sumx[b] + bias[o].
//
// R5 changes:
//  * W staged via cp.async.bulk (UBLKCP, 256B per row) into 4 SMEM slots,
//    320B row stride (conflict-free readback), per-warp mbarrier expect_tx
//    pipelines -> no LDGSTS issue cap, no cross-warp sync in the hot loop.
//  * x pre-split to a packed [k4][batch] hi/lo gmem array by a prep kernel;
//    fragment loads are coalesced LDG.128 that L1-hit (W bypasses L1).
// ---------------------------------------------------------------------------

#define PB       32
#define PIN      8192
#define POUT     16384
#define M_TILE   128
#define NTHREADS 256
#define NGRP     (PIN / 64)               // 128 k64 groups
#define NSLOT    4
#define WROWB    320u                      // smem bytes per W row (256 + 64 pad)
#define WSLOT    (128u * WROWB)            // 40960 B per slot
#define SM_MBAR  0u                        // 8 warps x 4 slots x 8B = 256B
#define SM_W     1024u
#define SMEM_BYTES (SM_W + NSLOT * WSLOT)  // 164864

__device__ float d_sumx[PB];
__device__ uint4 d_xhl[(PIN / 4) * PB];    // [k4][batch] packed hi/lo half2, 1MB

__device__ __forceinline__ uint32_t smem_u32(const void* p) {
    uint32_t a;
    asm("{ .reg .u64 t; cvta.to.shared.u64 t, %1; cvt.u32.u64 %0, t; }" : "=r"(a) : "l"(p));
    return a;
}

#define MBARRIER_INIT(addr, cnt) \
    asm volatile("mbarrier.init.shared.b64 [%0], %1;" :: "r"((uint32_t)(addr)), "r"((uint32_t)(cnt)) : "memory")

#define MBARRIER_EXPECT_TX(addr, bytes) \
    asm volatile("mbarrier.arrive.expect_tx.shared.b64 _, [%0], %1;" \
                 :: "r"((uint32_t)(addr)), "r"((uint32_t)(bytes)) : "memory")

#define MBARRIER_WAIT_PARITY(mbar_smem_addr, phase_parity) do {                                \
    uint32_t _mbar = (uint32_t)(mbar_smem_addr);                                               \
    uint32_t _parity = (uint32_t)(phase_parity);                                               \
    uint32_t _done;                                                                            \
    asm volatile(                                                                              \
        "{\n\t.reg .pred p;\n\t"                                                               \
        "mbarrier.try_wait.parity.acquire.cta.shared::cta.b64 p, [%1], %2;\n\t"                \
        "selp.b32 %0, 1, 0, p;\n\t}"                                                           \
        : "=r"(_done) : "r"(_mbar), "r"(_parity) : "memory");                                  \
    if (!_done) {                                                                              \
        asm volatile(                                                                          \
            "{\n\t.reg .pred P1;\n\t"                                                          \
            "WAIT_LOOP_%=:\n\t"                                                                \
            "mbarrier.try_wait.parity.acquire.cta.shared::cta.b64 P1, [%0], %1, 0x989680;\n\t" \
            "@P1 bra.uni WAIT_DONE_%=;\n\t"                                                    \
            "bra.uni WAIT_LOOP_%=;\n\t"                                                        \
            "WAIT_DONE_%=:\n\t}"                                                               \
            :: "r"(_mbar), "r"(_parity) : "memory");                                           \
    }                                                                                          \
} while (0)

__device__ __forceinline__ void cp_bulk_256(uint32_t dst, const void* src, uint32_t mbar) {
    asm volatile(
        "cp.async.bulk.shared::cluster.global.mbarrier::complete_tx::bytes [%0], [%1], 256, [%2];"
        :: "r"(dst), "l"(src), "r"(mbar) : "memory");
}

#define LDS128(r0, r1, r2, r3, addr)                                  \
    asm volatile("ld.shared.v4.b32 {%0,%1,%2,%3}, [%4];"              \
                 : "=r"(r0), "=r"(r1), "=r"(r2), "=r"(r3) : "r"(addr))

__device__ __forceinline__ void mma_f16(float* c,
                                        uint32_t a0, uint32_t a1, uint32_t a2, uint32_t a3,
                                        uint32_t b0, uint32_t b1) {
    asm volatile(
        "mma.sync.aligned.m16n8k16.row.col.f32.f16.f16.f32 "
        "{%0,%1,%2,%3}, {%4,%5,%6,%7}, {%8,%9}, {%0,%1,%2,%3};"
        : "+f"(c[0]), "+f"(c[1]), "+f"(c[2]), "+f"(c[3])
        : "r"(a0), "r"(a1), "r"(a2), "r"(a3), "r"(b0), "r"(b1));
}

// two int8 codes -> packed half2 of EXACT (idx-128)
__device__ __forceinline__ uint32_t packA(uint32_t i0, uint32_t i1, uint32_t off2) {
    uint32_t r = 0x64006400u | i0 | (i1 << 16);
    __half2 h = __hsub2(*reinterpret_cast<__half2*>(&r),
                        *reinterpret_cast<const __half2*>(&off2));
    return *reinterpret_cast<uint32_t*>(&h);
}

__device__ __forceinline__ uint4 split_x4(float4 v) {
    __half2 h0 = __floats2half2_rn(v.x, v.y);
    __half2 h1 = __floats2half2_rn(v.z, v.w);
    float2 f0 = __half22float2(h0);
    float2 f1 = __half22float2(h1);
    __half2 l0 = __floats2half2_rn(v.x - f0.x, v.y - f0.y);
    __half2 l1 = __floats2half2_rn(v.z - f1.x, v.w - f1.y);
    uint4 s;
    s.x = *reinterpret_cast<uint32_t*>(&h0);
    s.y = *reinterpret_cast<uint32_t*>(&h1);
    s.z = *reinterpret_cast<uint32_t*>(&l0);
    s.w = *reinterpret_cast<uint32_t*>(&l1);
    return s;
}

// ---- prep: pack x into [k4][batch] hi/lo ----
__global__ void prep_x_kernel(const float* __restrict__ x) {
    const int e  = blockIdx.x * 256 + threadIdx.x;   // 0..65535
    const int n  = e & 31;
    const int k4 = e >> 5;
    float4 v = __ldg(reinterpret_cast<const float4*>(x) + (size_t)n * (PIN / 4) + k4);
    d_xhl[(size_t)k4 * PB + n] = split_x4(v);
}

// ---- prep: per-batch row sums of x (affine c0 correction) ----
__global__ void sumx_kernel(const float* __restrict__ x) {
    __shared__ float red[8];
    const int b = blockIdx.x;
    const float4* xr = reinterpret_cast<const float4*>(x + (size_t)b * PIN);
    float s = 0.0f;
    for (int i = threadIdx.x; i < PIN / 4; i += 256) {
        float4 v = __ldg(xr + i);
        s += (v.x + v.y) + (v.z + v.w);
    }
    #pragma unroll
    for (int o = 16; o; o >>= 1) s += __shfl_xor_sync(0xFFFFFFFFu, s, o);
    if ((threadIdx.x & 31) == 0) red[threadIdx.x >> 5] = s;
    __syncthreads();
    if (threadIdx.x < 8) {
        s = red[threadIdx.x];
        #pragma unroll
        for (int o = 4; o; o >>= 1) s += __shfl_xor_sync(0xFFu, s, o);
        if (threadIdx.x == 0) d_sumx[b] = s;
    }
}

__global__ void __launch_bounds__(NTHREADS, 1)
linear_int8_mma_kernel(const float* __restrict__ x,
                       const float* __restrict__ lut,
                       const float* __restrict__ bias,
                       const int*   __restrict__ widx,
                       float*       __restrict__ out) {
    extern __shared__ __align__(1024) char smem[];
    const uint32_t sbase = smem_u32(smem);

    const int tid  = threadIdx.x;
    const int w    = tid >> 5;
    const int lane = tid & 31;
    const int g    = lane >> 2;       // fragment group: A row / B col
    const int q    = lane & 3;        // fragment k-slot

    const float l0 = __ldg(lut);
    const float sc = __ldg(lut + 1) - l0;
    const float c0 = fmaf(128.0f, sc, l0);
    const uint32_t off1152 = 0x64806480u;   // half2(1152,1152)

    // per-warp mbarriers (4 slots)
    const uint32_t mb_base = sbase + SM_MBAR + (uint32_t)w * 32u;
    if (lane == 0) {
        #pragma unroll
        for (int s = 0; s < NSLOT; ++s) MBARRIER_INIT(mb_base + 8u * s, 1);
        asm volatile("fence.proxy.async.shared::cta;" ::: "memory");
    }
    __syncthreads();

    // this warp owns tile rows w*16 .. w*16+15
    const int rbase = blockIdx.x * M_TILE + w * 16;
    const char* wrow = reinterpret_cast<const char*>(widx) + (size_t)rbase * PIN * 4;
    // smem base of this warp's rows within a slot
    const uint32_t wslot0 = sbase + SM_W + (uint32_t)(w * 16) * WROWB;

    // readback base for this thread: row (w*16+g), +q*16
    const uint32_t rd0 = sbase + SM_W + (uint32_t)(w * 16 + g) * WROWB + (uint32_t)q * 16u;

    float acc[4][4];
    #pragma unroll
    for (int t = 0; t < 4; ++t)
        #pragma unroll
        for (int i = 0; i < 4; ++i) acc[t][i] = 0.0f;

    // ---- prologue: issue grps 0..3 into slots 0..3 ----
    #pragma unroll
    for (int s = 0; s < NSLOT; ++s) {
        if (lane == 0) {
            const uint32_t mbar = mb_base + 8u * s;
            MBARRIER_EXPECT_TX(mbar, 16u * 256u);
            const uint32_t dst = wslot0 + (uint32_t)s * WSLOT;
            #pragma unroll
            for (int j = 0; j < 16; ++j) {
                cp_bulk_256(dst + (uint32_t)j * WROWB,
                            wrow + (size_t)j * (PIN * 4) + (size_t)s * 256, mbar);
            }
        }
    }

    // x fragment base offset for this thread (uint4 units): [k4][batch]
    const uint4* xfrag = d_xhl + (size_t)q * PB + (g);

    int slot = 0, par = 0;
    for (int G = 0; G < NGRP; ++G) {
        const uint32_t mbar = mb_base + 8u * slot;
        MBARRIER_WAIT_PARITY(mbar, par);

        // ---- W readback (conflict-free: 320B row stride) ----
        const uint32_t rb = rd0 + (uint32_t)slot * WSLOT;
        uint4 cur[8];
        #pragma unroll
        for (int u = 0; u < 4; ++u) {
            LDS128(cur[2*u].x,   cur[2*u].y,   cur[2*u].z,   cur[2*u].w,   rb + (uint32_t)u * 64u);
            LDS128(cur[2*u+1].x, cur[2*u+1].y, cur[2*u+1].z, cur[2*u+1].w, rb + (uint32_t)u * 64u + 8u * WROWB);
        }

        // ---- dequant (consumes LDS -> safe to overwrite slot afterwards) ----
        uint32_t A[16];
        #pragma unroll
        for (int u = 0; u < 4; ++u) {
            A[4*u + 0] = packA(cur[2*u].x,   cur[2*u].y,   off1152);
            A[4*u + 2] = packA(cur[2*u].z,   cur[2*u].w,   off1152);
            A[4*u + 1] = packA(cur[2*u+1].x, cur[2*u+1].y, off1152);
            A[4*u + 3] = packA(cur[2*u+1].z, cur[2*u+1].w, off1152);
        }

        // ---- refill this slot with grp G+4 ----
        if (G + 4 < NGRP && lane == 0) {
            MBARRIER_EXPECT_TX(mbar, 16u * 256u);
            const uint32_t dst = wslot0 + (uint32_t)slot * WSLOT;
            const size_t koff = (size_t)(G + 4) * 256;
            #pragma unroll
            for (int j = 0; j < 16; ++j) {
                cp_bulk_256(dst + (uint32_t)j * WROWB,
                            wrow + (size_t)j * (PIN * 4) + koff, mbar);
            }
        }

        // ---- x fragments (coalesced LDG.128, L1-resident) + MMA ----
        const uint4* xg = xfrag + (size_t)G * 16 * PB;
        #pragma unroll
        for (int u = 0; u < 4; ++u) {
            uint4 xv[4];
            #pragma unroll
            for (int t = 0; t < 4; ++t)
                xv[t] = __ldg(xg + (size_t)(u * 4) * PB + 8 * t);
            #pragma unroll
            for (int t = 0; t < 4; ++t) {
                mma_f16(acc[t], A[4*u], A[4*u+1], A[4*u+2], A[4*u+3], xv[t].x, xv[t].y);  // hi
                mma_f16(acc[t], A[4*u], A[4*u+1], A[4*u+2], A[4*u+3], xv[t].z, xv[t].w);  // lo
            }
        }

        if (++slot == NSLOT) { slot = 0; par ^= 1; }
    }

    // ---- epilogue: y = sc*acc + c0*sumx[b] + bias[o] ----
    const int o0 = rbase + g;
    const int o1 = o0 + 8;
    const float bv0 = __ldg(bias + o0);
    const float bv1 = __ldg(bias + o1);
    #pragma unroll
    for (int t = 0; t < 4; ++t) {
        const int n0 = 8 * t + 2 * q;
        const float s0 = d_sumx[n0];
        const float s1 = d_sumx[n0 + 1];
        out[(size_t)n0 * POUT + o0]       = fmaf(sc, acc[t][0], fmaf(c0, s0, bv0));
        out[(size_t)(n0 + 1) * POUT + o0] = fmaf(sc, acc[t][1], fmaf(c0, s1, bv0));
        out[(size_t)n0 * POUT + o1]       = fmaf(sc, acc[t][2], fmaf(c0, s0, bv1));
        out[(size_t)(n0 + 1) * POUT + o1] = fmaf(sc, acc[t][3], fmaf(c0, s1, bv1));
    }
}

extern "C" void kernel_launch(void* const* d_in, const int* in_sizes, int n_in,
                              void* d_out, int out_size) {
    const float* x = nullptr;
    const float* lut = nullptr;
    const float* bias = nullptr;
    const int*   widx = nullptr;
    for (int i = 0; i < n_in; ++i) {
        if (in_sizes[i] == PB * PIN)            x    = (const float*)d_in[i];
        else if (in_sizes[i] == 256)            lut  = (const float*)d_in[i];
        else if (in_sizes[i] == POUT)           bias = (const float*)d_in[i];
        else                                    widx = (const int*)d_in[i];
    }
    float* out = (float*)d_out;

    cudaFuncSetAttribute(linear_int8_mma_kernel,
                         cudaFuncAttributeMaxDynamicSharedMemorySize, SMEM_BYTES);
    prep_x_kernel<<<(PIN / 4) * PB / 256, 256>>>(x);
    sumx_kernel<<<PB, 256>>>(x);
    linear_int8_mma_kernel<<<POUT / M_TILE, NTHREADS, SMEM_BYTES>>>(
        x, lut, bias, widx, out);
}

// round 6
// speedup vs baseline: 1.0755x; 1.0755x over previous
#include <cuda_runtime.h>
#include <cuda_fp16.h>
#include <cstdint>

// ---------------------------------------------------------------------------
// y[b,o] = sum_i x[b,i] * lut[widx[o,i]] + bias[o]
//   B=32, IN=8192, OUT=16384 ; lut affine: lut[c] = lut[0] + c*(lut[1]-lut[0])
//
// Exact-precision fp16 MMA scheme (validated R3/R4/R5):
//   A = (idx-128) exact in fp16 via (0x6400|idx) -> 1024+idx, HSUB2 1152.
//   x = x_hi + x_lo fp16 split; 2x mma.m16n8k16.f16, fp32 accum.
//   y = sc*acc + c0*sumx[b] + bias[o].
//
// R6: back to per-thread 16B cp.async.cg for W (R4 transport; R5's 256B bulk
// copies were engine-overhead-bound). Changes vs R4:
//   * M_TILE=64, 128 threads, grid=256 -> 2 CTAs/SM, all 148 SMs active.
//   * x from prep'd [k4][batch] hi/lo gmem array (L1-hit LDG.128): no x smem
//     staging, no __syncthreads in the mainloop, warps fully decoupled.
//   * 5-slot (depth-5) per-thread cp.async pipeline, 320B W row stride
//     (conflict-free LDS.128 readback).
// ---------------------------------------------------------------------------

#define PB       32
#define PIN      8192
#define POUT     16384
#define M_TILE   64
#define NTHREADS 128
#define NGRP     (PIN / 64)               // 128 k64 groups
#define NSLOT    5
#define WROWB    320u                      // smem bytes per W row (256 + 64 pad)
#define WSLOT    (64u * WROWB)             // 20480 B per slot
#define SMEM_BYTES (NSLOT * WSLOT)         // 102400

__device__ float d_sumx[PB];
__device__ uint4 d_xhl[(PIN / 4) * PB];    // [k4][batch] packed hi/lo half2, 1MB

__device__ __forceinline__ uint32_t smem_u32(const void* p) {
    uint32_t a;
    asm("{ .reg .u64 t; cvta.to.shared.u64 t, %1; cvt.u32.u64 %0, t; }" : "=r"(a) : "l"(p));
    return a;
}

__device__ __forceinline__ void cpasync16(uint32_t dst, const void* src) {
    asm volatile("cp.async.cg.shared.global [%0], [%1], 16;" :: "r"(dst), "l"(src) : "memory");
}
#define CP_COMMIT() asm volatile("cp.async.commit_group;" ::: "memory")
#define CP_WAIT(n)  asm volatile("cp.async.wait_group %0;" :: "n"(n) : "memory")

#define LDS128(r0, r1, r2, r3, addr)                                  \
    asm volatile("ld.shared.v4.b32 {%0,%1,%2,%3}, [%4];"              \
                 : "=r"(r0), "=r"(r1), "=r"(r2), "=r"(r3) : "r"(addr))

__device__ __forceinline__ void mma_f16(float* c,
                                        uint32_t a0, uint32_t a1, uint32_t a2, uint32_t a3,
                                        uint32_t b0, uint32_t b1) {
    asm volatile(
        "mma.sync.aligned.m16n8k16.row.col.f32.f16.f16.f32 "
        "{%0,%1,%2,%3}, {%4,%5,%6,%7}, {%8,%9}, {%0,%1,%2,%3};"
        : "+f"(c[0]), "+f"(c[1]), "+f"(c[2]), "+f"(c[3])
        : "r"(a0), "r"(a1), "r"(a2), "r"(a3), "r"(b0), "r"(b1));
}

// two int8 codes -> packed half2 of EXACT (idx-128)
__device__ __forceinline__ uint32_t packA(uint32_t i0, uint32_t i1, uint32_t off2) {
    uint32_t r = 0x64006400u | i0 | (i1 << 16);
    __half2 h = __hsub2(*reinterpret_cast<__half2*>(&r),
                        *reinterpret_cast<const __half2*>(&off2));
    return *reinterpret_cast<uint32_t*>(&h);
}

__device__ __forceinline__ uint4 split_x4(float4 v) {
    __half2 h0 = __floats2half2_rn(v.x, v.y);
    __half2 h1 = __floats2half2_rn(v.z, v.w);
    float2 f0 = __half22float2(h0);
    float2 f1 = __half22float2(h1);
    __half2 l0 = __floats2half2_rn(v.x - f0.x, v.y - f0.y);
    __half2 l1 = __floats2half2_rn(v.z - f1.x, v.w - f1.y);
    uint4 s;
    s.x = *reinterpret_cast<uint32_t*>(&h0);
    s.y = *reinterpret_cast<uint32_t*>(&h1);
    s.z = *reinterpret_cast<uint32_t*>(&l0);
    s.w = *reinterpret_cast<uint32_t*>(&l1);
    return s;
}

// ---- prep: pack x into [k4][batch] hi/lo ----
__global__ void prep_x_kernel(const float* __restrict__ x) {
    const int e  = blockIdx.x * 256 + threadIdx.x;   // 0..65535
    const int n  = e & 31;
    const int k4 = e >> 5;
    float4 v = __ldg(reinterpret_cast<const float4*>(x) + (size_t)n * (PIN / 4) + k4);
    d_xhl[(size_t)k4 * PB + n] = split_x4(v);
}

// ---- prep: per-batch row sums of x (affine c0 correction) ----
__global__ void sumx_kernel(const float* __restrict__ x) {
    __shared__ float red[8];
    const int b = blockIdx.x;
    const float4* xr = reinterpret_cast<const float4*>(x + (size_t)b * PIN);
    float s = 0.0f;
    for (int i = threadIdx.x; i < PIN / 4; i += 256) {
        float4 v = __ldg(xr + i);
        s += (v.x + v.y) + (v.z + v.w);
    }
    #pragma unroll
    for (int o = 16; o; o >>= 1) s += __shfl_xor_sync(0xFFFFFFFFu, s, o);
    if ((threadIdx.x & 31) == 0) red[threadIdx.x >> 5] = s;
    __syncthreads();
    if (threadIdx.x < 8) {
        s = red[threadIdx.x];
        #pragma unroll
        for (int o = 4; o; o >>= 1) s += __shfl_xor_sync(0xFFu, s, o);
        if (threadIdx.x == 0) d_sumx[b] = s;
    }
}

__global__ void __launch_bounds__(NTHREADS, 2)
linear_int8_mma_kernel(const float* __restrict__ x,
                       const float* __restrict__ lut,
                       const float* __restrict__ bias,
                       const int*   __restrict__ widx,
                       float*       __restrict__ out) {
    extern __shared__ __align__(128) char smem[];
    const uint32_t sbase = smem_u32(smem);

    const int tid  = threadIdx.x;
    const int w    = tid >> 5;        // 0..3
    const int lane = tid & 31;
    const int g    = lane >> 2;       // fragment group: A row / B col
    const int q    = lane & 3;        // fragment k-slot

    const float l0 = __ldg(lut);
    const float sc = __ldg(lut + 1) - l0;
    const float c0 = fmaf(128.0f, sc, l0);
    const uint32_t off1152 = 0x64806480u;   // half2(1152,1152)

    // this warp owns tile rows w*16 .. w*16+15 of the CTA's 64-row tile
    const int rbase = blockIdx.x * M_TILE + w * 16;
    // this thread's two W rows (g and g+8) in global memory
    const char* wr0 = reinterpret_cast<const char*>(widx) + (size_t)(rbase + g) * PIN * 4;
    const char* wr1 = wr0 + (size_t)8 * PIN * 4;
    // smem: this thread copies/reads rows (w*16+g) and (+8), chunks q*16 + u*64
    const uint32_t sm0 = sbase + (uint32_t)(w * 16 + g) * WROWB + (uint32_t)q * 16u;
    const uint32_t sm1 = sm0 + 8u * WROWB;

    float acc[4][4];
    #pragma unroll
    for (int t = 0; t < 4; ++t)
        #pragma unroll
        for (int i = 0; i < 4; ++i) acc[t][i] = 0.0f;

    // ---- prologue: issue grps 0..4 into slots 0..4 ----
    #pragma unroll
    for (int s = 0; s < NSLOT; ++s) {
        const uint32_t d0 = sm0 + (uint32_t)s * WSLOT;
        const uint32_t d1 = sm1 + (uint32_t)s * WSLOT;
        const size_t koff = (size_t)s * 256 + (size_t)q * 16;
        #pragma unroll
        for (int u = 0; u < 4; ++u) {
            cpasync16(d0 + (uint32_t)u * 64u, wr0 + koff + (size_t)u * 64);
            cpasync16(d1 + (uint32_t)u * 64u, wr1 + koff + (size_t)u * 64);
        }
        CP_COMMIT();
    }

    // x fragment base for this thread (uint4 units): [k4][batch]
    const uint4* xfrag = d_xhl + (size_t)q * PB + g;

    int slot = 0;
    for (int G = 0; G < NGRP; ++G) {
        // wait until grp G's copies landed (per-thread)
        if (G <= NGRP - NSLOT)      { CP_WAIT(4); }
        else if (G == NGRP - 4)     { CP_WAIT(3); }
        else if (G == NGRP - 3)     { CP_WAIT(2); }
        else if (G == NGRP - 2)     { CP_WAIT(1); }
        else                        { CP_WAIT(0); }

        // ---- W readback (conflict-free: 320B row stride) ----
        const uint32_t r0 = sm0 + (uint32_t)slot * WSLOT;
        const uint32_t r1 = sm1 + (uint32_t)slot * WSLOT;
        uint4 cur[8];
        #pragma unroll
        for (int u = 0; u < 4; ++u) {
            LDS128(cur[2*u].x,   cur[2*u].y,   cur[2*u].z,   cur[2*u].w,   r0 + (uint32_t)u * 64u);
            LDS128(cur[2*u+1].x, cur[2*u+1].y, cur[2*u+1].z, cur[2*u+1].w, r1 + (uint32_t)u * 64u);
        }

        // ---- dequant ----
        uint32_t A[16];
        #pragma unroll
        for (int u = 0; u < 4; ++u) {
            A[4*u + 0] = packA(cur[2*u].x,   cur[2*u].y,   off1152);
            A[4*u + 2] = packA(cur[2*u].z,   cur[2*u].w,   off1152);
            A[4*u + 1] = packA(cur[2*u+1].x, cur[2*u+1].y, off1152);
            A[4*u + 3] = packA(cur[2*u+1].z, cur[2*u+1].w, off1152);
        }

        // ---- refill this slot with grp G+5 ----
        if (G + NSLOT < NGRP) {
            const uint32_t d0 = r0;
            const uint32_t d1 = r1;
            const size_t koff = (size_t)(G + NSLOT) * 256 + (size_t)q * 16;
            #pragma unroll
            for (int u = 0; u < 4; ++u) {
                cpasync16(d0 + (uint32_t)u * 64u, wr0 + koff + (size_t)u * 64);
                cpasync16(d1 + (uint32_t)u * 64u, wr1 + koff + (size_t)u * 64);
            }
            CP_COMMIT();
        }

        // ---- x fragments (coalesced LDG.128, L1-resident) + MMA ----
        const uint4* xg = xfrag + (size_t)G * 16 * PB;
        #pragma unroll
        for (int u = 0; u < 4; ++u) {
            uint4 xv[4];
            #pragma unroll
            for (int t = 0; t < 4; ++t)
                xv[t] = __ldg(xg + (size_t)(u * 4) * PB + 8 * t);
            #pragma unroll
            for (int t = 0; t < 4; ++t) {
                mma_f16(acc[t], A[4*u], A[4*u+1], A[4*u+2], A[4*u+3], xv[t].x, xv[t].y);  // hi
                mma_f16(acc[t], A[4*u], A[4*u+1], A[4*u+2], A[4*u+3], xv[t].z, xv[t].w);  // lo
            }
        }

        if (++slot == NSLOT) slot = 0;
    }

    // ---- epilogue: y = sc*acc + c0*sumx[b] + bias[o] ----
    const int o0 = rbase + g;
    const int o1 = o0 + 8;
    const float bv0 = __ldg(bias + o0);
    const float bv1 = __ldg(bias + o1);
    #pragma unroll
    for (int t = 0; t < 4; ++t) {
        const int n0 = 8 * t + 2 * q;
        const float s0 = d_sumx[n0];
        const float s1 = d_sumx[n0 + 1];
        out[(size_t)n0 * POUT + o0]       = fmaf(sc, acc[t][0], fmaf(c0, s0, bv0));
        out[(size_t)(n0 + 1) * POUT + o0] = fmaf(sc, acc[t][1], fmaf(c0, s1, bv0));
        out[(size_t)n0 * POUT + o1]       = fmaf(sc, acc[t][2], fmaf(c0, s0, bv1));
        out[(size_t)(n0 + 1) * POUT + o1] = fmaf(sc, acc[t][3], fmaf(c0, s1, bv1));
    }
}

extern "C" void kernel_launch(void* const* d_in, const int* in_sizes, int n_in,
                              void* d_out, int out_size) {
    const float* x = nullptr;
    const float* lut = nullptr;
    const float* bias = nullptr;
    const int*   widx = nullptr;
    for (int i = 0; i < n_in; ++i) {
        if (in_sizes[i] == PB * PIN)            x    = (const float*)d_in[i];
        else if (in_sizes[i] == 256)            lut  = (const float*)d_in[i];
        else if (in_sizes[i] == POUT)           bias = (const float*)d_in[i];
        else                                    widx = (const int*)d_in[i];
    }
    float* out = (float*)d_out;

    cudaFuncSetAttribute(linear_int8_mma_kernel,
                         cudaFuncAttributeMaxDynamicSharedMemorySize, SMEM_BYTES);
    prep_x_kernel<<<(PIN / 4) * PB / 256, 256>>>(x);
    sumx_kernel<<<PB, 256>>>(x);
    linear_int8_mma_kernel<<<POUT / M_TILE, NTHREADS, SMEM_BYTES>>>(
        x, lut, bias, widx, out);
}

// round 7
// speedup vs baseline: 2.2365x; 2.0795x over previous
#include <cuda_runtime.h>
#include <cuda_fp16.h>
#include <cstdint>

// ---------------------------------------------------------------------------
// y[b,o] = sum_i x[b,i] * lut[widx[o,i]] + bias[o]
//   B=32, IN=8192, OUT=16384 ; lut affine: lut[c] = lut[0] + c*(lut[1]-lut[0])
//
// Exact-precision fp16 MMA scheme (validated R3/R4):
//   A = (idx-128) exact in fp16 via (0x6400|idx) -> 1024+idx, HSUB2 1152.
//   x = x_hi + x_lo fp16 split; 2x mma.m16n8k16.f16, fp32 accum.
//   y = sc*acc + c0*sumx[b] + bias[o].
//
// R7: statically-balanced persistent grid of 148 CTAs (R4 ran grid=128 ->
// >13% of SMs idle; any uniform re-tiling keeps makespan at total/128 by
// wave quantization). Work = 4096 flat (tile,k256-chunk) units; CTA b takes
// units [b*4096/148, (b+1)*4096/148) -- 27/28 units, 1.2% imbalance. The
// cp.async W pipeline runs continuously across tile boundaries; only the
// accumulator is flushed (atomicAdd/RED) at a tile change (<=2 per CTA).
// out is pre-initialized with bias + c0*sumx by a tiny init kernel.
// Inner loop identical to R4 (113.4us, rel_err 1.76e-5).
// ---------------------------------------------------------------------------

#define PB       32
#define PIN      8192
#define POUT     16384
#define NTHREADS 256
#define NCTA     148
#define NTILE    128                       // 16384 / 128 rows
#define CH_PER_TILE 32                     // k256 chunks per tile
#define NUNIT    (NTILE * CH_PER_TILE)     // 4096 flat chunks
#define EPC      68                        // uint4 entries per x col (64 + 4 pad)
#define BUF_U4   (PB * EPC)                // 2176 uint4 per x buffer
#define SM_W     (2 * BUF_U4 * 16)         // 69632 : W staging base
#define WSTAGE   32768                     // 32KB per grp slot (256 thr * 128B)
#define SMEM_BYTES (SM_W + 4 * WSTAGE)     // 200704

__device__ float d_sumx[PB];

__device__ __forceinline__ uint32_t smem_u32(const void* p) {
    uint32_t a;
    asm("{ .reg .u64 t; cvta.to.shared.u64 t, %1; cvt.u32.u64 %0, t; }" : "=r"(a) : "l"(p));
    return a;
}

__device__ __forceinline__ void cpasync16(uint32_t dst, const void* src) {
    asm volatile("cp.async.cg.shared.global [%0], [%1], 16;" :: "r"(dst), "l"(src) : "memory");
}
#define CP_COMMIT() asm volatile("cp.async.commit_group;" ::: "memory")
#define CP_WAIT(n)  asm volatile("cp.async.wait_group %0;" :: "n"(n) : "memory")

#define LDS128(r0, r1, r2, r3, addr)                                  \
    asm volatile("ld.shared.v4.b32 {%0,%1,%2,%3}, [%4];"              \
                 : "=r"(r0), "=r"(r1), "=r"(r2), "=r"(r3) : "r"(addr))

__device__ __forceinline__ void mma_f16(float* c,
                                        uint32_t a0, uint32_t a1, uint32_t a2, uint32_t a3,
                                        uint32_t b0, uint32_t b1) {
    asm volatile(
        "mma.sync.aligned.m16n8k16.row.col.f32.f16.f16.f32 "
        "{%0,%1,%2,%3}, {%4,%5,%6,%7}, {%8,%9}, {%0,%1,%2,%3};"
        : "+f"(c[0]), "+f"(c[1]), "+f"(c[2]), "+f"(c[3])
        : "r"(a0), "r"(a1), "r"(a2), "r"(a3), "r"(b0), "r"(b1));
}

// two int8 codes -> packed half2 of EXACT (idx-128)
__device__ __forceinline__ uint32_t packA(uint32_t i0, uint32_t i1, uint32_t off2) {
    uint32_t r = 0x64006400u | i0 | (i1 << 16);
    __half2 h = __hsub2(*reinterpret_cast<__half2*>(&r),
                        *reinterpret_cast<const __half2*>(&off2));
    return *reinterpret_cast<uint32_t*>(&h);
}

__device__ __forceinline__ uint4 split_x4(float4 v) {
    __half2 h0 = __floats2half2_rn(v.x, v.y);
    __half2 h1 = __floats2half2_rn(v.z, v.w);
    float2 f0 = __half22float2(h0);
    float2 f1 = __half22float2(h1);
    __half2 l0 = __floats2half2_rn(v.x - f0.x, v.y - f0.y);
    __half2 l1 = __floats2half2_rn(v.z - f1.x, v.w - f1.y);
    uint4 s;
    s.x = *reinterpret_cast<uint32_t*>(&h0);
    s.y = *reinterpret_cast<uint32_t*>(&h1);
    s.z = *reinterpret_cast<uint32_t*>(&l0);
    s.w = *reinterpret_cast<uint32_t*>(&l1);
    return s;
}

// ---- prep: per-batch row sums of x (affine c0 correction) ----
__global__ void sumx_kernel(const float* __restrict__ x) {
    __shared__ float red[8];
    const int b = blockIdx.x;
    const float4* xr = reinterpret_cast<const float4*>(x + (size_t)b * PIN);
    float s = 0.0f;
    for (int i = threadIdx.x; i < PIN / 4; i += 256) {
        float4 v = __ldg(xr + i);
        s += (v.x + v.y) + (v.z + v.w);
    }
    #pragma unroll
    for (int o = 16; o; o >>= 1) s += __shfl_xor_sync(0xFFFFFFFFu, s, o);
    if ((threadIdx.x & 31) == 0) red[threadIdx.x >> 5] = s;
    __syncthreads();
    if (threadIdx.x < 8) {
        s = red[threadIdx.x];
        #pragma unroll
        for (int o = 4; o; o >>= 1) s += __shfl_xor_sync(0xFFu, s, o);
        if (threadIdx.x == 0) d_sumx[b] = s;
    }
}

// ---- prep: out[b,o] = bias[o] + c0*sumx[b] ----
__global__ void init_out_kernel(const float* __restrict__ lut,
                                const float* __restrict__ bias,
                                float* __restrict__ out) {
    const int i = blockIdx.x * 256 + threadIdx.x;          // 0..524287
    const float l0 = __ldg(lut);
    const float sc = __ldg(lut + 1) - l0;
    const float c0 = fmaf(128.0f, sc, l0);
    const int o = i & (POUT - 1);
    const int b = i >> 14;
    out[i] = fmaf(c0, d_sumx[b], __ldg(bias + o));
}

__global__ void __launch_bounds__(NTHREADS, 1)
linear_int8_mma_kernel(const float* __restrict__ x,
                       const float* __restrict__ lut,
                       const float* __restrict__ bias,
                       const int*   __restrict__ widx,
                       float*       __restrict__ out) {
    extern __shared__ __align__(16) uint4 xs[];   // x: 2 buffers ; W: 4 slots
    const uint32_t sbase = smem_u32(xs);

    const int tid  = threadIdx.x;
    const int w    = tid >> 5;
    const int lane = tid & 31;
    const int g    = lane >> 2;       // fragment group: A row / B col
    const int q    = lane & 3;        // fragment k-slot

    const float l0 = __ldg(lut);
    const float sc = __ldg(lut + 1) - l0;
    const uint32_t off1152 = 0x64806480u;   // half2(1152,1152)

    // ---- this CTA's flat chunk range [s, e) ----
    const int s = (int)(((unsigned)blockIdx.x * NUNIT) / NCTA);
    const int e = (int)((((unsigned)blockIdx.x + 1) * NUNIT) / NCTA);
    const int gs = s * 4;
    const int ge = e * 4;

    // per-thread W staging slot base (reads back its own copies)
    const uint32_t wsl = sbase + SM_W + (uint32_t)w * 4096u + (uint32_t)lane * 16u;

    // W source for flat grp fg (int4 units): rows (tile*128 + w*16 + g) / +8
    const int4* wbase = reinterpret_cast<const int4*>(widx);
    const int rowsub = w * 16 + g;

    float acc[4][4];
    #pragma unroll
    for (int t = 0; t < 4; ++t)
        #pragma unroll
        for (int i = 0; i < 4; ++i) acc[t][i] = 0.0f;

    // ---- prologue: issue W grps gs..gs+3 into slots 0..3 ----
    #pragma unroll
    for (int sidx = 0; sidx < 4; ++sidx) {
        const int fg = gs + sidx;
        const int4* p = wbase + (size_t)((fg >> 7) * 128 + rowsub) * (PIN / 4)
                              + ((fg & 127) << 4) + q;
        const uint32_t ds = wsl + (uint32_t)sidx * WSTAGE;
        #pragma unroll
        for (int u = 0; u < 4; ++u) {
            cpasync16(ds + (uint32_t)(2 * u) * 512u,     p + 4 * u);
            cpasync16(ds + (uint32_t)(2 * u + 1) * 512u, p + 8 * (PIN / 4) + 4 * u);
        }
        CP_COMMIT();
    }

    // ---- stage x chunk s ----
    const float4* xg = reinterpret_cast<const float4*>(x);
    #pragma unroll
    for (int j = 0; j < 8; ++j) {
        const int f  = tid + 256 * j;
        const int n  = f >> 6;
        const int kg = f & 63;
        float4 v = __ldg(xg + (size_t)n * (PIN / 4) + (s & 31) * 64 + kg);
        xs[(s & 1) * BUF_U4 + n * EPC + kg] = split_x4(v);
    }
    __syncthreads();

    int cur_tile = s >> 5;

    for (int c = s; c < e; ++c) {
        const int t_tile = c >> 5;
        if (t_tile != cur_tile) {
            // flush accumulator for cur_tile (RED.ADD, no return)
            const int o0 = cur_tile * NTILE + rowsub;
            #pragma unroll
            for (int t = 0; t < 4; ++t) {
                const int n0 = 8 * t + 2 * q;
                atomicAdd(&out[(size_t)n0 * POUT + o0],           sc * acc[t][0]);
                atomicAdd(&out[(size_t)(n0 + 1) * POUT + o0],     sc * acc[t][1]);
                atomicAdd(&out[(size_t)n0 * POUT + o0 + 8],       sc * acc[t][2]);
                atomicAdd(&out[(size_t)(n0 + 1) * POUT + o0 + 8], sc * acc[t][3]);
                acc[t][0] = acc[t][1] = acc[t][2] = acc[t][3] = 0.0f;
            }
            cur_tile = t_tile;
        }

        const uint4* xb = &xs[(c & 1) * BUF_U4];

        // prefetch next x chunk into registers (stored after compute)
        float4 xr[8];
        if (c + 1 < e) {
            const int kofs = ((c + 1) & 31) * 64;
            #pragma unroll
            for (int j = 0; j < 8; ++j) {
                const int f  = tid + 256 * j;
                const int n  = f >> 6;
                const int kg = f & 63;
                xr[j] = __ldg(xg + (size_t)n * (PIN / 4) + kofs + kg);
            }
        }

        #pragma unroll
        for (int sub = 0; sub < 4; ++sub) {
            const int fg = c * 4 + sub;
            const int rem = ge - fg;
            if (rem > 3)        { CP_WAIT(3); }
            else if (rem == 3)  { CP_WAIT(2); }
            else if (rem == 2)  { CP_WAIT(1); }
            else                { CP_WAIT(0); }

            // ---- W readback (slot = fg & 3 = sub, since gs % 4 == 0) ----
            const uint32_t sl = wsl + (uint32_t)sub * WSTAGE;
            uint4 cur[8];
            #pragma unroll
            for (int j = 0; j < 8; ++j) {
                LDS128(cur[j].x, cur[j].y, cur[j].z, cur[j].w, sl + (uint32_t)j * 512u);
            }

            // ---- dequant ----
            uint32_t A[16];
            #pragma unroll
            for (int u = 0; u < 4; ++u) {
                A[4*u + 0] = packA(cur[2*u].x,   cur[2*u].y,   off1152);
                A[4*u + 2] = packA(cur[2*u].z,   cur[2*u].w,   off1152);
                A[4*u + 1] = packA(cur[2*u+1].x, cur[2*u+1].y, off1152);
                A[4*u + 3] = packA(cur[2*u+1].z, cur[2*u+1].w, off1152);
            }

            // ---- refill this slot with grp fg+4 (crosses tiles seamlessly) ----
            if (fg + 4 < ge) {
                const int fn = fg + 4;
                const int4* p = wbase + (size_t)((fn >> 7) * 128 + rowsub) * (PIN / 4)
                                      + ((fn & 127) << 4) + q;
                #pragma unroll
                for (int u = 0; u < 4; ++u) {
                    cpasync16(sl + (uint32_t)(2 * u) * 512u,     p + 4 * u);
                    cpasync16(sl + (uint32_t)(2 * u + 1) * 512u, p + 8 * (PIN / 4) + 4 * u);
                }
                CP_COMMIT();
            }

            // ---- x fragments (smem, conflict-free) + MMA ----
            #pragma unroll
            for (int u = 0; u < 4; ++u) {
                const int entry = (sub * 4 + u) * 4 + q;
                uint4 xv[4];
                #pragma unroll
                for (int t = 0; t < 4; ++t)
                    xv[t] = xb[(g + 8 * t) * EPC + entry];
                #pragma unroll
                for (int t = 0; t < 4; ++t) {
                    mma_f16(acc[t], A[4*u], A[4*u+1], A[4*u+2], A[4*u+3], xv[t].x, xv[t].y);
                    mma_f16(acc[t], A[4*u], A[4*u+1], A[4*u+2], A[4*u+3], xv[t].z, xv[t].w);
                }
            }
        }

        // store prefetched x into the other buffer
        if (c + 1 < e) {
            uint4* db = &xs[((c + 1) & 1) * BUF_U4];
            #pragma unroll
            for (int j = 0; j < 8; ++j) {
                const int f  = tid + 256 * j;
                const int n  = f >> 6;
                const int kg = f & 63;
                db[n * EPC + kg] = split_x4(xr[j]);
            }
        }
        __syncthreads();
    }

    // ---- final flush ----
    {
        const int o0 = cur_tile * NTILE + rowsub;
        #pragma unroll
        for (int t = 0; t < 4; ++t) {
            const int n0 = 8 * t + 2 * q;
            atomicAdd(&out[(size_t)n0 * POUT + o0],           sc * acc[t][0]);
            atomicAdd(&out[(size_t)(n0 + 1) * POUT + o0],     sc * acc[t][1]);
            atomicAdd(&out[(size_t)n0 * POUT + o0 + 8],       sc * acc[t][2]);
            atomicAdd(&out[(size_t)(n0 + 1) * POUT + o0 + 8], sc * acc[t][3]);
        }
    }
}

extern "C" void kernel_launch(void* const* d_in, const int* in_sizes, int n_in,
                              void* d_out, int out_size) {
    const float* x = nullptr;
    const float* lut = nullptr;
    const float* bias = nullptr;
    const int*   widx = nullptr;
    for (int i = 0; i < n_in; ++i) {
        if (in_sizes[i] == PB * PIN)            x    = (const float*)d_in[i];
        else if (in_sizes[i] == 256)            lut  = (const float*)d_in[i];
        else if (in_sizes[i] == POUT)           bias = (const float*)d_in[i];
        else                                    widx = (const int*)d_in[i];
    }
    float* out = (float*)d_out;

    cudaFuncSetAttribute(linear_int8_mma_kernel,
                         cudaFuncAttributeMaxDynamicSharedMemorySize, SMEM_BYTES);
    sumx_kernel<<<PB, 256>>>(x);
    init_out_kernel<<<(PB * POUT) / 256, 256>>>(lut, bias, out);
    linear_int8_mma_kernel<<<NCTA, NTHREADS, SMEM_BYTES>>>(x, lut, bias, widx, out);
}

// round 8
// speedup vs baseline: 2.2776x; 1.0184x over previous
#include <cuda_runtime.h>
#include <cuda_fp16.h>
#include <cstdint>

// ---------------------------------------------------------------------------
// y[b,o] = sum_i x[b,i] * lut[widx[o,i]] + bias[o]
//   B=32, IN=8192, OUT=16384 ; lut affine: lut[c] = lut[0] + c*(lut[1]-lut[0])
//
// Exact-precision fp16 MMA scheme (validated R3..R7):
//   A = (idx-128) exact in fp16 via (0x6400|idx) -> 1024+idx, HSUB2 1152.
//   x = x_hi + x_lo fp16 split; 2x mma.m16n8k16.f16, fp32 accum.
//   out preinit = bias[o] + c0*sumx[b]; GEMM adds sc*acc atomically.
//
// R8: fuse the two prep kernels (sumx 7.8us @grid32 + init_out ~3us) into ONE
// grid-128 kernel (~3us): each of 4 blocks per batch row recomputes sumx[b]
// (32KB, L2-hot, bit-identical) and writes its quarter of the preinit row.
// Main persistent GEMM kernel is byte-identical to R7 (104.6us validated).
// ---------------------------------------------------------------------------

#define PB       32
#define PIN      8192
#define POUT     16384
#define NTHREADS 256
#define NCTA     148
#define NTILE    128                       // rows per tile
#define NUNIT    4096                      // 128 tiles * 32 k256-chunks
#define EPC      68                        // uint4 entries per x col (64 + 4 pad)
#define BUF_U4   (PB * EPC)                // 2176 uint4 per x buffer
#define SM_W     (2 * BUF_U4 * 16)         // 69632 : W staging base
#define WSTAGE   32768                     // 32KB per grp slot
#define SMEM_BYTES (SM_W + 4 * WSTAGE)     // 200704

__device__ __forceinline__ uint32_t smem_u32(const void* p) {
    uint32_t a;
    asm("{ .reg .u64 t; cvta.to.shared.u64 t, %1; cvt.u32.u64 %0, t; }" : "=r"(a) : "l"(p));
    return a;
}

__device__ __forceinline__ void cpasync16(uint32_t dst, const void* src) {
    asm volatile("cp.async.cg.shared.global [%0], [%1], 16;" :: "r"(dst), "l"(src) : "memory");
}
#define CP_COMMIT() asm volatile("cp.async.commit_group;" ::: "memory")
#define CP_WAIT(n)  asm volatile("cp.async.wait_group %0;" :: "n"(n) : "memory")

#define LDS128(r0, r1, r2, r3, addr)                                  \
    asm volatile("ld.shared.v4.b32 {%0,%1,%2,%3}, [%4];"              \
                 : "=r"(r0), "=r"(r1), "=r"(r2), "=r"(r3) : "r"(addr))

__device__ __forceinline__ void mma_f16(float* c,
                                        uint32_t a0, uint32_t a1, uint32_t a2, uint32_t a3,
                                        uint32_t b0, uint32_t b1) {
    asm volatile(
        "mma.sync.aligned.m16n8k16.row.col.f32.f16.f16.f32 "
        "{%0,%1,%2,%3}, {%4,%5,%6,%7}, {%8,%9}, {%0,%1,%2,%3};"
        : "+f"(c[0]), "+f"(c[1]), "+f"(c[2]), "+f"(c[3])
        : "r"(a0), "r"(a1), "r"(a2), "r"(a3), "r"(b0), "r"(b1));
}

// two int8 codes -> packed half2 of EXACT (idx-128)
__device__ __forceinline__ uint32_t packA(uint32_t i0, uint32_t i1, uint32_t off2) {
    uint32_t r = 0x64006400u | i0 | (i1 << 16);
    __half2 h = __hsub2(*reinterpret_cast<__half2*>(&r),
                        *reinterpret_cast<const __half2*>(&off2));
    return *reinterpret_cast<uint32_t*>(&h);
}

__device__ __forceinline__ uint4 split_x4(float4 v) {
    __half2 h0 = __floats2half2_rn(v.x, v.y);
    __half2 h1 = __floats2half2_rn(v.z, v.w);
    float2 f0 = __half22float2(h0);
    float2 f1 = __half22float2(h1);
    __half2 l0 = __floats2half2_rn(v.x - f0.x, v.y - f0.y);
    __half2 l1 = __floats2half2_rn(v.z - f1.x, v.w - f1.y);
    uint4 s;
    s.x = *reinterpret_cast<uint32_t*>(&h0);
    s.y = *reinterpret_cast<uint32_t*>(&h1);
    s.z = *reinterpret_cast<uint32_t*>(&l0);
    s.w = *reinterpret_cast<uint32_t*>(&l1);
    return s;
}

// ---- fused prep: out[b, o] = bias[o] + c0*sumx[b] ----
// grid = 4*PB blocks; block (b, quarter) recomputes sumx[b] (bit-identical
// across the 4 blocks of a row) and writes its quarter of out row b.
__global__ void prep_out_kernel(const float* __restrict__ x,
                                const float* __restrict__ lut,
                                const float* __restrict__ bias,
                                float* __restrict__ out) {
    __shared__ float red[8];
    const int b       = blockIdx.x >> 2;
    const int quarter = blockIdx.x & 3;

    // block-wide sum of x[b, :]
    const float4* xr = reinterpret_cast<const float4*>(x + (size_t)b * PIN);
    float s = 0.0f;
    #pragma unroll
    for (int j = 0; j < (PIN / 4) / 256; ++j) {            // 8 iters
        float4 v = __ldg(xr + threadIdx.x + 256 * j);
        s += (v.x + v.y) + (v.z + v.w);
    }
    #pragma unroll
    for (int o = 16; o; o >>= 1) s += __shfl_xor_sync(0xFFFFFFFFu, s, o);
    if ((threadIdx.x & 31) == 0) red[threadIdx.x >> 5] = s;
    __syncthreads();
    {
        float t = red[0];
        #pragma unroll
        for (int k = 1; k < 8; ++k) t += red[k];
        s = t;                                             // deterministic order
    }

    const float l0 = __ldg(lut);
    const float sc = __ldg(lut + 1) - l0;
    const float c0 = fmaf(128.0f, sc, l0);
    const float addv = c0 * s;

    // write quarter of out row b: 4096 floats = 4 float4 per thread
    const int obase = quarter * (POUT / 4);
    const float4* bq = reinterpret_cast<const float4*>(bias + obase);
    float4* oq = reinterpret_cast<float4*>(out + (size_t)b * POUT + obase);
    #pragma unroll
    for (int j = 0; j < (POUT / 4) / 4 / 256; ++j) {       // 4 iters
        float4 bv = __ldg(bq + threadIdx.x + 256 * j);
        bv.x += addv; bv.y += addv; bv.z += addv; bv.w += addv;
        oq[threadIdx.x + 256 * j] = bv;
    }
}

__global__ void __launch_bounds__(NTHREADS, 1)
linear_int8_mma_kernel(const float* __restrict__ x,
                       const float* __restrict__ lut,
                       const float* __restrict__ bias,
                       const int*   __restrict__ widx,
                       float*       __restrict__ out) {
    extern __shared__ __align__(16) uint4 xs[];   // x: 2 buffers ; W: 4 slots
    const uint32_t sbase = smem_u32(xs);

    const int tid  = threadIdx.x;
    const int w    = tid >> 5;
    const int lane = tid & 31;
    const int g    = lane >> 2;       // fragment group: A row / B col
    const int q    = lane & 3;        // fragment k-slot

    const float l0 = __ldg(lut);
    const float sc = __ldg(lut + 1) - l0;
    const uint32_t off1152 = 0x64806480u;   // half2(1152,1152)

    // ---- this CTA's flat chunk range [s, e) ----
    const int s = (int)(((unsigned)blockIdx.x * NUNIT) / NCTA);
    const int e = (int)((((unsigned)blockIdx.x + 1) * NUNIT) / NCTA);
    const int ge = e * 4;

    // per-thread W staging slot base (reads back its own copies)
    const uint32_t wsl = sbase + SM_W + (uint32_t)w * 4096u + (uint32_t)lane * 16u;

    const int4* wbase = reinterpret_cast<const int4*>(widx);
    const int rowsub = w * 16 + g;

    float acc[4][4];
    #pragma unroll
    for (int t = 0; t < 4; ++t)
        #pragma unroll
        for (int i = 0; i < 4; ++i) acc[t][i] = 0.0f;

    // ---- prologue: issue W grps s*4 .. s*4+3 into slots 0..3 ----
    #pragma unroll
    for (int sidx = 0; sidx < 4; ++sidx) {
        const int fg = s * 4 + sidx;
        const int4* p = wbase + (size_t)((fg >> 7) * 128 + rowsub) * (PIN / 4)
                              + ((fg & 127) << 4) + q;
        const uint32_t ds = wsl + (uint32_t)sidx * WSTAGE;
        #pragma unroll
        for (int u = 0; u < 4; ++u) {
            cpasync16(ds + (uint32_t)(2 * u) * 512u,     p + 4 * u);
            cpasync16(ds + (uint32_t)(2 * u + 1) * 512u, p + 8 * (PIN / 4) + 4 * u);
        }
        CP_COMMIT();
    }

    // ---- stage x chunk s ----
    const float4* xg = reinterpret_cast<const float4*>(x);
    #pragma unroll
    for (int j = 0; j < 8; ++j) {
        const int f  = tid + 256 * j;
        const int n  = f >> 6;
        const int kg = f & 63;
        float4 v = __ldg(xg + (size_t)n * (PIN / 4) + (s & 31) * 64 + kg);
        xs[(s & 1) * BUF_U4 + n * EPC + kg] = split_x4(v);
    }
    __syncthreads();

    int cur_tile = s >> 5;

    for (int c = s; c < e; ++c) {
        const int t_tile = c >> 5;
        if (t_tile != cur_tile) {
            // flush accumulator for cur_tile (RED.ADD, no return)
            const int o0 = cur_tile * NTILE + rowsub;
            #pragma unroll
            for (int t = 0; t < 4; ++t) {
                const int n0 = 8 * t + 2 * q;
                atomicAdd(&out[(size_t)n0 * POUT + o0],           sc * acc[t][0]);
                atomicAdd(&out[(size_t)(n0 + 1) * POUT + o0],     sc * acc[t][1]);
                atomicAdd(&out[(size_t)n0 * POUT + o0 + 8],       sc * acc[t][2]);
                atomicAdd(&out[(size_t)(n0 + 1) * POUT + o0 + 8], sc * acc[t][3]);
                acc[t][0] = acc[t][1] = acc[t][2] = acc[t][3] = 0.0f;
            }
            cur_tile = t_tile;
        }

        const uint4* xb = &xs[(c & 1) * BUF_U4];

        // prefetch next x chunk into registers (stored after compute)
        float4 xr[8];
        if (c + 1 < e) {
            const int kofs = ((c + 1) & 31) * 64;
            #pragma unroll
            for (int j = 0; j < 8; ++j) {
                const int f  = tid + 256 * j;
                const int n  = f >> 6;
                const int kg = f & 63;
                xr[j] = __ldg(xg + (size_t)n * (PIN / 4) + kofs + kg);
            }
        }

        #pragma unroll
        for (int sub = 0; sub < 4; ++sub) {
            const int fg = c * 4 + sub;
            const int rem = ge - fg;
            if (rem > 3)        { CP_WAIT(3); }
            else if (rem == 3)  { CP_WAIT(2); }
            else if (rem == 2)  { CP_WAIT(1); }
            else                { CP_WAIT(0); }

            // ---- W readback (slot = sub: CTA ranges start 4-aligned) ----
            const uint32_t sl = wsl + (uint32_t)sub * WSTAGE;
            uint4 cur[8];
            #pragma unroll
            for (int j = 0; j < 8; ++j) {
                LDS128(cur[j].x, cur[j].y, cur[j].z, cur[j].w, sl + (uint32_t)j * 512u);
            }

            // ---- dequant ----
            uint32_t A[16];
            #pragma unroll
            for (int u = 0; u < 4; ++u) {
                A[4*u + 0] = packA(cur[2*u].x,   cur[2*u].y,   off1152);
                A[4*u + 2] = packA(cur[2*u].z,   cur[2*u].w,   off1152);
                A[4*u + 1] = packA(cur[2*u+1].x, cur[2*u+1].y, off1152);
                A[4*u + 3] = packA(cur[2*u+1].z, cur[2*u+1].w, off1152);
            }

            // ---- refill this slot with grp fg+4 (crosses tiles seamlessly) ----
            if (fg + 4 < ge) {
                const int fn = fg + 4;
                const int4* p = wbase + (size_t)((fn >> 7) * 128 + rowsub) * (PIN / 4)
                                      + ((fn & 127) << 4) + q;
                #pragma unroll
                for (int u = 0; u < 4; ++u) {
                    cpasync16(sl + (uint32_t)(2 * u) * 512u,     p + 4 * u);
                    cpasync16(sl + (uint32_t)(2 * u + 1) * 512u, p + 8 * (PIN / 4) + 4 * u);
                }
                CP_COMMIT();
            }

            // ---- x fragments (smem, conflict-free) + MMA ----
            #pragma unroll
            for (int u = 0; u < 4; ++u) {
                const int entry = (sub * 4 + u) * 4 + q;
                uint4 xv[4];
                #pragma unroll
                for (int t = 0; t < 4; ++t)
                    xv[t] = xb[(g + 8 * t) * EPC + entry];
                #pragma unroll
                for (int t = 0; t < 4; ++t) {
                    mma_f16(acc[t], A[4*u], A[4*u+1], A[4*u+2], A[4*u+3], xv[t].x, xv[t].y);
                    mma_f16(acc[t], A[4*u], A[4*u+1], A[4*u+2], A[4*u+3], xv[t].z, xv[t].w);
                }
            }
        }

        // store prefetched x into the other buffer
        if (c + 1 < e) {
            uint4* db = &xs[((c + 1) & 1) * BUF_U4];
            #pragma unroll
            for (int j = 0; j < 8; ++j) {
                const int f  = tid + 256 * j;
                const int n  = f >> 6;
                const int kg = f & 63;
                db[n * EPC + kg] = split_x4(xr[j]);
            }
        }
        __syncthreads();
    }

    // ---- final flush ----
    {
        const int o0 = cur_tile * NTILE + rowsub;
        #pragma unroll
        for (int t = 0; t < 4; ++t) {
            const int n0 = 8 * t + 2 * q;
            atomicAdd(&out[(size_t)n0 * POUT + o0],           sc * acc[t][0]);
            atomicAdd(&out[(size_t)(n0 + 1) * POUT + o0],     sc * acc[t][1]);
            atomicAdd(&out[(size_t)n0 * POUT + o0 + 8],       sc * acc[t][2]);
            atomicAdd(&out[(size_t)(n0 + 1) * POUT + o0 + 8], sc * acc[t][3]);
        }
    }
}

extern "C" void kernel_launch(void* const* d_in, const int* in_sizes, int n_in,
                              void* d_out, int out_size) {
    const float* x = nullptr;
    const float* lut = nullptr;
    const float* bias = nullptr;
    const int*   widx = nullptr;
    for (int i = 0; i < n_in; ++i) {
        if (in_sizes[i] == PB * PIN)            x    = (const float*)d_in[i];
        else if (in_sizes[i] == 256)            lut  = (const float*)d_in[i];
        else if (in_sizes[i] == POUT)           bias = (const float*)d_in[i];
        else                                    widx = (const int*)d_in[i];
    }
    float* out = (float*)d_out;

    cudaFuncSetAttribute(linear_int8_mma_kernel,
                         cudaFuncAttributeMaxDynamicSharedMemorySize, SMEM_BYTES);
    prep_out_kernel<<<4 * PB, 256>>>(x, lut, bias, out);
    linear_int8_mma_kernel<<<NCTA, NTHREADS, SMEM_BYTES>>>(x, lut, bias, widx, out);
}

// round 9
// speedup vs baseline: 2.4691x; 1.0841x over previous
#include <cuda_runtime.h>
#include <cuda_fp16.h>
#include <cstdint>

// ---------------------------------------------------------------------------
// y[b,o] = sum_i x[b,i] * lut[widx[o,i]] + bias[o]
//   B=32, IN=8192, OUT=16384 ; lut affine: lut[c] = lut[0] + c*(lut[1]-lut[0])
//
// Exact-precision fp16 MMA scheme (validated R3..R8):
//   A = (idx-128) exact in fp16 via (0x6400|idx) -> 1024+idx, HSUB2 1152.
//   x = x_hi + x_lo fp16 split; 2x mma.m16n8k16.f16, fp32 accum.
//   out preinit = bias[o] + c0*sumx[b]; GEMM adds sc*acc atomically.
//
// R9: m32 per warp (two m16 tiles share each x fragment) -> x smem reads per
// W-byte halve; crossbar demand -27%. M_TILE=256, k32 W-groups staged at
// exact 128B row stride with XOR swizzle chunk = q + 4*(s ^ (g&1))
// (conflict-free LDS.128 readback, no padding). Persistent 148 CTAs over
// 2048 (tile, k256-chunk) units. Transport identical to R8 (per-thread
// cp.async.cg 16B, depth-4 slots, per-thread wait_group).
// ---------------------------------------------------------------------------

#define PB       32
#define PIN      8192
#define POUT     16384
#define NTHREADS 256
#define NCTA     148
#define TROWS    256                       // rows per tile
#define NUNIT    2048                      // 64 tiles * 32 k256-chunks
#define EPC      68                        // uint4 entries per x col (64 + 4 pad)
#define BUF_U4   (PB * EPC)                // 2176 uint4 per x buffer
#define SM_W     (2 * BUF_U4 * 16)         // 69632 : W staging base
#define WSLOT    32768u                    // 256 rows * 128 B (k32 group)
#define SMEM_BYTES (SM_W + 4 * WSLOT)      // 200704

__device__ __forceinline__ uint32_t smem_u32(const void* p) {
    uint32_t a;
    asm("{ .reg .u64 t; cvta.to.shared.u64 t, %1; cvt.u32.u64 %0, t; }" : "=r"(a) : "l"(p));
    return a;
}

__device__ __forceinline__ void cpasync16(uint32_t dst, const void* src) {
    asm volatile("cp.async.cg.shared.global [%0], [%1], 16;" :: "r"(dst), "l"(src) : "memory");
}
#define CP_COMMIT() asm volatile("cp.async.commit_group;" ::: "memory")
#define CP_WAIT(n)  asm volatile("cp.async.wait_group %0;" :: "n"(n) : "memory")

#define LDS128(r0, r1, r2, r3, addr)                                  \
    asm volatile("ld.shared.v4.b32 {%0,%1,%2,%3}, [%4];"              \
                 : "=r"(r0), "=r"(r1), "=r"(r2), "=r"(r3) : "r"(addr))

__device__ __forceinline__ void mma_f16(float* c,
                                        uint32_t a0, uint32_t a1, uint32_t a2, uint32_t a3,
                                        uint32_t b0, uint32_t b1) {
    asm volatile(
        "mma.sync.aligned.m16n8k16.row.col.f32.f16.f16.f32 "
        "{%0,%1,%2,%3}, {%4,%5,%6,%7}, {%8,%9}, {%0,%1,%2,%3};"
        : "+f"(c[0]), "+f"(c[1]), "+f"(c[2]), "+f"(c[3])
        : "r"(a0), "r"(a1), "r"(a2), "r"(a3), "r"(b0), "r"(b1));
}

// two int8 codes -> packed half2 of EXACT (idx-128)
__device__ __forceinline__ uint32_t packA(uint32_t i0, uint32_t i1, uint32_t off2) {
    uint32_t r = 0x64006400u | i0 | (i1 << 16);
    __half2 h = __hsub2(*reinterpret_cast<__half2*>(&r),
                        *reinterpret_cast<const __half2*>(&off2));
    return *reinterpret_cast<uint32_t*>(&h);
}

__device__ __forceinline__ uint4 split_x4(float4 v) {
    __half2 h0 = __floats2half2_rn(v.x, v.y);
    __half2 h1 = __floats2half2_rn(v.z, v.w);
    float2 f0 = __half22float2(h0);
    float2 f1 = __half22float2(h1);
    __half2 l0 = __floats2half2_rn(v.x - f0.x, v.y - f0.y);
    __half2 l1 = __floats2half2_rn(v.z - f1.x, v.w - f1.y);
    uint4 s;
    s.x = *reinterpret_cast<uint32_t*>(&h0);
    s.y = *reinterpret_cast<uint32_t*>(&h1);
    s.z = *reinterpret_cast<uint32_t*>(&l0);
    s.w = *reinterpret_cast<uint32_t*>(&l1);
    return s;
}

// ---- fused prep: out[b, o] = bias[o] + c0*sumx[b] (grid = 4*PB) ----
__global__ void prep_out_kernel(const float* __restrict__ x,
                                const float* __restrict__ lut,
                                const float* __restrict__ bias,
                                float* __restrict__ out) {
    __shared__ float red[8];
    const int b       = blockIdx.x >> 2;
    const int quarter = blockIdx.x & 3;

    const float4* xr = reinterpret_cast<const float4*>(x + (size_t)b * PIN);
    float s = 0.0f;
    #pragma unroll
    for (int j = 0; j < (PIN / 4) / 256; ++j) {
        float4 v = __ldg(xr + threadIdx.x + 256 * j);
        s += (v.x + v.y) + (v.z + v.w);
    }
    #pragma unroll
    for (int o = 16; o; o >>= 1) s += __shfl_xor_sync(0xFFFFFFFFu, s, o);
    if ((threadIdx.x & 31) == 0) red[threadIdx.x >> 5] = s;
    __syncthreads();
    {
        float t = red[0];
        #pragma unroll
        for (int k = 1; k < 8; ++k) t += red[k];
        s = t;                                             // deterministic order
    }

    const float l0 = __ldg(lut);
    const float sc = __ldg(lut + 1) - l0;
    const float c0 = fmaf(128.0f, sc, l0);
    const float addv = c0 * s;

    const int obase = quarter * (POUT / 4);
    const float4* bq = reinterpret_cast<const float4*>(bias + obase);
    float4* oq = reinterpret_cast<float4*>(out + (size_t)b * POUT + obase);
    #pragma unroll
    for (int j = 0; j < (POUT / 4) / 4 / 256; ++j) {
        float4 bv = __ldg(bq + threadIdx.x + 256 * j);
        bv.x += addv; bv.y += addv; bv.z += addv; bv.w += addv;
        oq[threadIdx.x + 256 * j] = bv;
    }
}

__global__ void __launch_bounds__(NTHREADS, 1)
linear_int8_mma_kernel(const float* __restrict__ x,
                       const float* __restrict__ lut,
                       const float* __restrict__ bias,
                       const int*   __restrict__ widx,
                       float*       __restrict__ out) {
    extern __shared__ __align__(16) uint4 xs[];   // x: 2 buffers ; W: 4 slots
    const uint32_t sbase = smem_u32(xs);

    const int tid  = threadIdx.x;
    const int w    = tid >> 5;
    const int lane = tid & 31;
    const int g    = lane >> 2;       // fragment group: A row / B col
    const int q    = lane & 3;        // fragment k-slot

    const float l0 = __ldg(lut);
    const float sc = __ldg(lut + 1) - l0;
    const uint32_t off1152 = 0x64806480u;   // half2(1152,1152)

    // ---- this CTA's flat k256-chunk range [s, e) ----
    const int s = (int)(((unsigned)blockIdx.x * NUNIT) / NCTA);
    const int e = (int)((((unsigned)blockIdx.x + 1) * NUNIT) / NCTA);
    const int ge = e * 8;                      // k32-group end

    // warp covers rows rowsub + {0,8,16,24} of the 256-row tile
    const int rowsub = w * 32 + g;
    const int4* wbase = reinterpret_cast<const int4*>(widx);

    // W smem: row stride exactly 128B; XOR swizzle chunk = q + 4*(s ^ (g&1))
    const uint32_t sw0 = 64u * (uint32_t)(g & 1);   // step-0 offset
    const uint32_t sw1 = 64u ^ sw0;                 // step-1 offset
    const uint32_t thr_off = sbase + SM_W + (uint32_t)rowsub * 128u + (uint32_t)q * 16u;

    float acc[2][4][4];
    #pragma unroll
    for (int h = 0; h < 2; ++h)
        #pragma unroll
        for (int t = 0; t < 4; ++t)
            #pragma unroll
            for (int i = 0; i < 4; ++i) acc[h][t][i] = 0.0f;

    // ---- prologue: issue k32-grps s*8 .. s*8+3 into slots 0..3 ----
    #pragma unroll
    for (int sidx = 0; sidx < 4; ++sidx) {
        const int fg = s * 8 + sidx;
        const int4* p = wbase + (size_t)((fg >> 8) * TROWS + rowsub) * (PIN / 4)
                              + ((fg & 255) << 3) + q;
        const uint32_t ds = thr_off + (uint32_t)sidx * WSLOT;
        #pragma unroll
        for (int j = 0; j < 4; ++j) {
            cpasync16(ds + (uint32_t)j * 1024u + sw0, p + (size_t)(8 * j) * (PIN / 4));
            cpasync16(ds + (uint32_t)j * 1024u + sw1, p + (size_t)(8 * j) * (PIN / 4) + 4);
        }
        CP_COMMIT();
    }

    // ---- stage x chunk s ----
    const float4* xg = reinterpret_cast<const float4*>(x);
    #pragma unroll
    for (int j = 0; j < 8; ++j) {
        const int f  = tid + 256 * j;
        const int n  = f >> 6;
        const int kg = f & 63;
        float4 v = __ldg(xg + (size_t)n * (PIN / 4) + (s & 31) * 64 + kg);
        xs[(s & 1) * BUF_U4 + n * EPC + kg] = split_x4(v);
    }
    __syncthreads();

    int cur_tile = s >> 5;

    for (int c = s; c < e; ++c) {
        const int t_tile = c >> 5;
        if (t_tile != cur_tile) {
            // flush both m16 tiles (RED.ADD, no return)
            #pragma unroll
            for (int h = 0; h < 2; ++h) {
                const int o0 = cur_tile * TROWS + rowsub + 16 * h;
                #pragma unroll
                for (int t = 0; t < 4; ++t) {
                    const int n0 = 8 * t + 2 * q;
                    atomicAdd(&out[(size_t)n0 * POUT + o0],           sc * acc[h][t][0]);
                    atomicAdd(&out[(size_t)(n0 + 1) * POUT + o0],     sc * acc[h][t][1]);
                    atomicAdd(&out[(size_t)n0 * POUT + o0 + 8],       sc * acc[h][t][2]);
                    atomicAdd(&out[(size_t)(n0 + 1) * POUT + o0 + 8], sc * acc[h][t][3]);
                    acc[h][t][0] = acc[h][t][1] = acc[h][t][2] = acc[h][t][3] = 0.0f;
                }
            }
            cur_tile = t_tile;
        }

        const uint4* xb = &xs[(c & 1) * BUF_U4];

        // prefetch next x chunk into registers (stored after compute)
        float4 xr[8];
        if (c + 1 < e) {
            const int kofs = ((c + 1) & 31) * 64;
            #pragma unroll
            for (int j = 0; j < 8; ++j) {
                const int f  = tid + 256 * j;
                const int n  = f >> 6;
                const int kg = f & 63;
                xr[j] = __ldg(xg + (size_t)n * (PIN / 4) + kofs + kg);
            }
        }

        #pragma unroll
        for (int sub = 0; sub < 8; ++sub) {
            const int fg = c * 8 + sub;
            const int rem = ge - fg;
            if (rem > 3)        { CP_WAIT(3); }
            else if (rem == 3)  { CP_WAIT(2); }
            else if (rem == 2)  { CP_WAIT(1); }
            else                { CP_WAIT(0); }

            // ---- W readback: 4 rows x 2 k16-steps (conflict-free) ----
            const uint32_t rb = thr_off + (uint32_t)(sub & 3) * WSLOT;
            uint4 cw[4][2];
            #pragma unroll
            for (int j = 0; j < 4; ++j) {
                LDS128(cw[j][0].x, cw[j][0].y, cw[j][0].z, cw[j][0].w,
                       rb + (uint32_t)j * 1024u + sw0);
                LDS128(cw[j][1].x, cw[j][1].y, cw[j][1].z, cw[j][1].w,
                       rb + (uint32_t)j * 1024u + sw1);
            }

            // ---- refill this slot with grp fg+4 ----
            if (fg + 4 < ge) {
                const int fn = fg + 4;
                const int4* p = wbase + (size_t)((fn >> 8) * TROWS + rowsub) * (PIN / 4)
                                      + ((fn & 255) << 3) + q;
                #pragma unroll
                for (int j = 0; j < 4; ++j) {
                    cpasync16(rb + (uint32_t)j * 1024u + sw0, p + (size_t)(8 * j) * (PIN / 4));
                    cpasync16(rb + (uint32_t)j * 1024u + sw1, p + (size_t)(8 * j) * (PIN / 4) + 4);
                }
                CP_COMMIT();
            }

            // ---- dequant + MMA per k16 step; x fragment shared by 2 m-tiles ----
            #pragma unroll
            for (int st = 0; st < 2; ++st) {
                const uint32_t A00 = packA(cw[0][st].x, cw[0][st].y, off1152);
                const uint32_t A02 = packA(cw[0][st].z, cw[0][st].w, off1152);
                const uint32_t A01 = packA(cw[1][st].x, cw[1][st].y, off1152);
                const uint32_t A03 = packA(cw[1][st].z, cw[1][st].w, off1152);
                const uint32_t A10 = packA(cw[2][st].x, cw[2][st].y, off1152);
                const uint32_t A12 = packA(cw[2][st].z, cw[2][st].w, off1152);
                const uint32_t A11 = packA(cw[3][st].x, cw[3][st].y, off1152);
                const uint32_t A13 = packA(cw[3][st].z, cw[3][st].w, off1152);

                const int entry = (sub * 2 + st) * 4 + q;
                #pragma unroll
                for (int t = 0; t < 4; ++t) {
                    const uint4 xv = xb[(g + 8 * t) * EPC + entry];
                    mma_f16(acc[0][t], A00, A01, A02, A03, xv.x, xv.y);
                    mma_f16(acc[0][t], A00, A01, A02, A03, xv.z, xv.w);
                    mma_f16(acc[1][t], A10, A11, A12, A13, xv.x, xv.y);
                    mma_f16(acc[1][t], A10, A11, A12, A13, xv.z, xv.w);
                }
            }
        }

        // store prefetched x into the other buffer
        if (c + 1 < e) {
            uint4* db = &xs[((c + 1) & 1) * BUF_U4];
            #pragma unroll
            for (int j = 0; j < 8; ++j) {
                const int f  = tid + 256 * j;
                const int n  = f >> 6;
                const int kg = f & 63;
                db[n * EPC + kg] = split_x4(xr[j]);
            }
        }
        __syncthreads();
    }

    // ---- final flush ----
    #pragma unroll
    for (int h = 0; h < 2; ++h) {
        const int o0 = cur_tile * TROWS + rowsub + 16 * h;
        #pragma unroll
        for (int t = 0; t < 4; ++t) {
            const int n0 = 8 * t + 2 * q;
            atomicAdd(&out[(size_t)n0 * POUT + o0],           sc * acc[h][t][0]);
            atomicAdd(&out[(size_t)(n0 + 1) * POUT + o0],     sc * acc[h][t][1]);
            atomicAdd(&out[(size_t)n0 * POUT + o0 + 8],       sc * acc[h][t][2]);
            atomicAdd(&out[(size_t)(n0 + 1) * POUT + o0 + 8], sc * acc[h][t][3]);
        }
    }
}

extern "C" void kernel_launch(void* const* d_in, const int* in_sizes, int n_in,
                              void* d_out, int out_size) {
    const float* x = nullptr;
    const float* lut = nullptr;
    const float* bias = nullptr;
    const int*   widx = nullptr;
    for (int i = 0; i < n_in; ++i) {
        if (in_sizes[i] == PB * PIN)            x    = (const float*)d_in[i];
        else if (in_sizes[i] == 256)            lut  = (const float*)d_in[i];
        else if (in_sizes[i] == POUT)           bias = (const float*)d_in[i];
        else                                    widx = (const int*)d_in[i];
    }
    float* out = (float*)d_out;

    cudaFuncSetAttribute(linear_int8_mma_kernel,
                         cudaFuncAttributeMaxDynamicSharedMemorySize, SMEM_BYTES);
    prep_out_kernel<<<4 * PB, 256>>>(x, lut, bias, out);
    linear_int8_mma_kernel<<<NCTA, NTHREADS, SMEM_BYTES>>>(x, lut, bias, widx, out);
}

// round 10
// speedup vs baseline: 2.4817x; 1.0051x over previous
#include <cuda_runtime.h>
#include <cuda_fp16.h>
#include <cstdint>

// ---------------------------------------------------------------------------
// y[b,o] = sum_i x[b,i] * lut[widx[o,i]] + bias[o]
//   B=32, IN=8192, OUT=16384 ; lut affine: lut[c] = lut[0] + c*(lut[1]-lut[0])
//
// Exact-precision fp16 MMA scheme (validated R3..R9):
//   A = (idx-128) exact in fp16 via (0x6400|idx) -> 1024+idx, HSUB2 1152.
//   x = x_hi + x_lo fp16 split; 2x mma.m16n8k16.f16, fp32 accum.
//   out preinit = bias[o] + c0*sumx[b]; GEMM adds sc*acc atomically.
//
// R10: R9 + L2::256B prefetch on the W cp.async stream. The W walk is
// row-sequential at 128B per slot per row, so each slot's 16B copies
// auto-prefetch the next two slots' lines into L2 -> refill waits become
// L2 hits instead of DRAM round trips, filling the latency gaps around
// the x-staging barrier that kept DRAM at 75%.
// ---------------------------------------------------------------------------

#define PB       32
#define PIN      8192
#define POUT     16384
#define NTHREADS 256
#define NCTA     148
#define TROWS    256                       // rows per tile
#define NUNIT    2048                      // 64 tiles * 32 k256-chunks
#define EPC      68                        // uint4 entries per x col (64 + 4 pad)
#define BUF_U4   (PB * EPC)                // 2176 uint4 per x buffer
#define SM_W     (2 * BUF_U4 * 16)         // 69632 : W staging base
#define WSLOT    32768u                    // 256 rows * 128 B (k32 group)
#define SMEM_BYTES (SM_W + 4 * WSLOT)      // 200704

__device__ __forceinline__ uint32_t smem_u32(const void* p) {
    uint32_t a;
    asm("{ .reg .u64 t; cvta.to.shared.u64 t, %1; cvt.u32.u64 %0, t; }" : "=r"(a) : "l"(p));
    return a;
}

__device__ __forceinline__ void cpasync16(uint32_t dst, const void* src) {
    asm volatile("cp.async.cg.shared.global.L2::256B [%0], [%1], 16;"
                 :: "r"(dst), "l"(src) : "memory");
}
#define CP_COMMIT() asm volatile("cp.async.commit_group;" ::: "memory")
#define CP_WAIT(n)  asm volatile("cp.async.wait_group %0;" :: "n"(n) : "memory")

#define LDS128(r0, r1, r2, r3, addr)                                  \
    asm volatile("ld.shared.v4.b32 {%0,%1,%2,%3}, [%4];"              \
                 : "=r"(r0), "=r"(r1), "=r"(r2), "=r"(r3) : "r"(addr))

__device__ __forceinline__ void mma_f16(float* c,
                                        uint32_t a0, uint32_t a1, uint32_t a2, uint32_t a3,
                                        uint32_t b0, uint32_t b1) {
    asm volatile(
        "mma.sync.aligned.m16n8k16.row.col.f32.f16.f16.f32 "
        "{%0,%1,%2,%3}, {%4,%5,%6,%7}, {%8,%9}, {%0,%1,%2,%3};"
        : "+f"(c[0]), "+f"(c[1]), "+f"(c[2]), "+f"(c[3])
        : "r"(a0), "r"(a1), "r"(a2), "r"(a3), "r"(b0), "r"(b1));
}

// two int8 codes -> packed half2 of EXACT (idx-128)
__device__ __forceinline__ uint32_t packA(uint32_t i0, uint32_t i1, uint32_t off2) {
    uint32_t r = 0x64006400u | i0 | (i1 << 16);
    __half2 h = __hsub2(*reinterpret_cast<__half2*>(&r),
                        *reinterpret_cast<const __half2*>(&off2));
    return *reinterpret_cast<uint32_t*>(&h);
}

__device__ __forceinline__ uint4 split_x4(float4 v) {
    __half2 h0 = __floats2half2_rn(v.x, v.y);
    __half2 h1 = __floats2half2_rn(v.z, v.w);
    float2 f0 = __half22float2(h0);
    float2 f1 = __half22float2(h1);
    __half2 l0 = __floats2half2_rn(v.x - f0.x, v.y - f0.y);
    __half2 l1 = __floats2half2_rn(v.z - f1.x, v.w - f1.y);
    uint4 s;
    s.x = *reinterpret_cast<uint32_t*>(&h0);
    s.y = *reinterpret_cast<uint32_t*>(&h1);
    s.z = *reinterpret_cast<uint32_t*>(&l0);
    s.w = *reinterpret_cast<uint32_t*>(&l1);
    return s;
}

// ---- fused prep: out[b, o] = bias[o] + c0*sumx[b] (grid = 4*PB) ----
__global__ void prep_out_kernel(const float* __restrict__ x,
                                const float* __restrict__ lut,
                                const float* __restrict__ bias,
                                float* __restrict__ out) {
    __shared__ float red[8];
    const int b       = blockIdx.x >> 2;
    const int quarter = blockIdx.x & 3;

    const float4* xr = reinterpret_cast<const float4*>(x + (size_t)b * PIN);
    float s = 0.0f;
    #pragma unroll
    for (int j = 0; j < (PIN / 4) / 256; ++j) {
        float4 v = __ldg(xr + threadIdx.x + 256 * j);
        s += (v.x + v.y) + (v.z + v.w);
    }
    #pragma unroll
    for (int o = 16; o; o >>= 1) s += __shfl_xor_sync(0xFFFFFFFFu, s, o);
    if ((threadIdx.x & 31) == 0) red[threadIdx.x >> 5] = s;
    __syncthreads();
    {
        float t = red[0];
        #pragma unroll
        for (int k = 1; k < 8; ++k) t += red[k];
        s = t;                                             // deterministic order
    }

    const float l0 = __ldg(lut);
    const float sc = __ldg(lut + 1) - l0;
    const float c0 = fmaf(128.0f, sc, l0);
    const float addv = c0 * s;

    const int obase = quarter * (POUT / 4);
    const float4* bq = reinterpret_cast<const float4*>(bias + obase);
    float4* oq = reinterpret_cast<float4*>(out + (size_t)b * POUT + obase);
    #pragma unroll
    for (int j = 0; j < (POUT / 4) / 4 / 256; ++j) {
        float4 bv = __ldg(bq + threadIdx.x + 256 * j);
        bv.x += addv; bv.y += addv; bv.z += addv; bv.w += addv;
        oq[threadIdx.x + 256 * j] = bv;
    }
}

__global__ void __launch_bounds__(NTHREADS, 1)
linear_int8_mma_kernel(const float* __restrict__ x,
                       const float* __restrict__ lut,
                       const float* __restrict__ bias,
                       const int*   __restrict__ widx,
                       float*       __restrict__ out) {
    extern __shared__ __align__(16) uint4 xs[];   // x: 2 buffers ; W: 4 slots
    const uint32_t sbase = smem_u32(xs);

    const int tid  = threadIdx.x;
    const int w    = tid >> 5;
    const int lane = tid & 31;
    const int g    = lane >> 2;       // fragment group: A row / B col
    const int q    = lane & 3;        // fragment k-slot

    const float l0 = __ldg(lut);
    const float sc = __ldg(lut + 1) - l0;
    const uint32_t off1152 = 0x64806480u;   // half2(1152,1152)

    // ---- this CTA's flat k256-chunk range [s, e) ----
    const int s = (int)(((unsigned)blockIdx.x * NUNIT) / NCTA);
    const int e = (int)((((unsigned)blockIdx.x + 1) * NUNIT) / NCTA);
    const int ge = e * 8;                      // k32-group end

    // warp covers rows rowsub + {0,8,16,24} of the 256-row tile
    const int rowsub = w * 32 + g;
    const int4* wbase = reinterpret_cast<const int4*>(widx);

    // W smem: row stride exactly 128B; XOR swizzle chunk = q + 4*(s ^ (g&1))
    const uint32_t sw0 = 64u * (uint32_t)(g & 1);   // step-0 offset
    const uint32_t sw1 = 64u ^ sw0;                 // step-1 offset
    const uint32_t thr_off = sbase + SM_W + (uint32_t)rowsub * 128u + (uint32_t)q * 16u;

    float acc[2][4][4];
    #pragma unroll
    for (int h = 0; h < 2; ++h)
        #pragma unroll
        for (int t = 0; t < 4; ++t)
            #pragma unroll
            for (int i = 0; i < 4; ++i) acc[h][t][i] = 0.0f;

    // ---- prologue: issue k32-grps s*8 .. s*8+3 into slots 0..3 ----
    #pragma unroll
    for (int sidx = 0; sidx < 4; ++sidx) {
        const int fg = s * 8 + sidx;
        const int4* p = wbase + (size_t)((fg >> 8) * TROWS + rowsub) * (PIN / 4)
                              + ((fg & 255) << 3) + q;
        const uint32_t ds = thr_off + (uint32_t)sidx * WSLOT;
        #pragma unroll
        for (int j = 0; j < 4; ++j) {
            cpasync16(ds + (uint32_t)j * 1024u + sw0, p + (size_t)(8 * j) * (PIN / 4));
            cpasync16(ds + (uint32_t)j * 1024u + sw1, p + (size_t)(8 * j) * (PIN / 4) + 4);
        }
        CP_COMMIT();
    }

    // ---- stage x chunk s ----
    const float4* xg = reinterpret_cast<const float4*>(x);
    #pragma unroll
    for (int j = 0; j < 8; ++j) {
        const int f  = tid + 256 * j;
        const int n  = f >> 6;
        const int kg = f & 63;
        float4 v = __ldg(xg + (size_t)n * (PIN / 4) + (s & 31) * 64 + kg);
        xs[(s & 1) * BUF_U4 + n * EPC + kg] = split_x4(v);
    }
    __syncthreads();

    int cur_tile = s >> 5;

    for (int c = s; c < e; ++c) {
        const int t_tile = c >> 5;
        if (t_tile != cur_tile) {
            // flush both m16 tiles (RED.ADD, no return)
            #pragma unroll
            for (int h = 0; h < 2; ++h) {
                const int o0 = cur_tile * TROWS + rowsub + 16 * h;
                #pragma unroll
                for (int t = 0; t < 4; ++t) {
                    const int n0 = 8 * t + 2 * q;
                    atomicAdd(&out[(size_t)n0 * POUT + o0],           sc * acc[h][t][0]);
                    atomicAdd(&out[(size_t)(n0 + 1) * POUT + o0],     sc * acc[h][t][1]);
                    atomicAdd(&out[(size_t)n0 * POUT + o0 + 8],       sc * acc[h][t][2]);
                    atomicAdd(&out[(size_t)(n0 + 1) * POUT + o0 + 8], sc * acc[h][t][3]);
                    acc[h][t][0] = acc[h][t][1] = acc[h][t][2] = acc[h][t][3] = 0.0f;
                }
            }
            cur_tile = t_tile;
        }

        const uint4* xb = &xs[(c & 1) * BUF_U4];

        // prefetch next x chunk into registers (stored after compute)
        float4 xr[8];
        if (c + 1 < e) {
            const int kofs = ((c + 1) & 31) * 64;
            #pragma unroll
            for (int j = 0; j < 8; ++j) {
                const int f  = tid + 256 * j;
                const int n  = f >> 6;
                const int kg = f & 63;
                xr[j] = __ldg(xg + (size_t)n * (PIN / 4) + kofs + kg);
            }
        }

        #pragma unroll
        for (int sub = 0; sub < 8; ++sub) {
            const int fg = c * 8 + sub;
            const int rem = ge - fg;
            if (rem > 3)        { CP_WAIT(3); }
            else if (rem == 3)  { CP_WAIT(2); }
            else if (rem == 2)  { CP_WAIT(1); }
            else                { CP_WAIT(0); }

            // ---- W readback: 4 rows x 2 k16-steps (conflict-free) ----
            const uint32_t rb = thr_off + (uint32_t)(sub & 3) * WSLOT;
            uint4 cw[4][2];
            #pragma unroll
            for (int j = 0; j < 4; ++j) {
                LDS128(cw[j][0].x, cw[j][0].y, cw[j][0].z, cw[j][0].w,
                       rb + (uint32_t)j * 1024u + sw0);
                LDS128(cw[j][1].x, cw[j][1].y, cw[j][1].z, cw[j][1].w,
                       rb + (uint32_t)j * 1024u + sw1);
            }

            // ---- refill this slot with grp fg+4 ----
            if (fg + 4 < ge) {
                const int fn = fg + 4;
                const int4* p = wbase + (size_t)((fn >> 8) * TROWS + rowsub) * (PIN / 4)
                                      + ((fn & 255) << 3) + q;
                #pragma unroll
                for (int j = 0; j < 4; ++j) {
                    cpasync16(rb + (uint32_t)j * 1024u + sw0, p + (size_t)(8 * j) * (PIN / 4));
                    cpasync16(rb + (uint32_t)j * 1024u + sw1, p + (size_t)(8 * j) * (PIN / 4) + 4);
                }
                CP_COMMIT();
            }

            // ---- dequant + MMA per k16 step; x fragment shared by 2 m-tiles ----
            #pragma unroll
            for (int st = 0; st < 2; ++st) {
                const uint32_t A00 = packA(cw[0][st].x, cw[0][st].y, off1152);
                const uint32_t A02 = packA(cw[0][st].z, cw[0][st].w, off1152);
                const uint32_t A01 = packA(cw[1][st].x, cw[1][st].y, off1152);
                const uint32_t A03 = packA(cw[1][st].z, cw[1][st].w, off1152);
                const uint32_t A10 = packA(cw[2][st].x, cw[2][st].y, off1152);
                const uint32_t A12 = packA(cw[2][st].z, cw[2][st].w, off1152);
                const uint32_t A11 = packA(cw[3][st].x, cw[3][st].y, off1152);
                const uint32_t A13 = packA(cw[3][st].z, cw[3][st].w, off1152);

                const int entry = (sub * 2 + st) * 4 + q;
                #pragma unroll
                for (int t = 0; t < 4; ++t) {
                    const uint4 xv = xb[(g + 8 * t) * EPC + entry];
                    mma_f16(acc[0][t], A00, A01, A02, A03, xv.x, xv.y);
                    mma_f16(acc[0][t], A00, A01, A02, A03, xv.z, xv.w);
                    mma_f16(acc[1][t], A10, A11, A12, A13, xv.x, xv.y);
                    mma_f16(acc[1][t], A10, A11, A12, A13, xv.z, xv.w);
                }
            }
        }

        // store prefetched x into the other buffer
        if (c + 1 < e) {
            uint4* db = &xs[((c + 1) & 1) * BUF_U4];
            #pragma unroll
            for (int j = 0; j < 8; ++j) {
                const int f  = tid + 256 * j;
                const int n  = f >> 6;
                const int kg = f & 63;
                db[n * EPC + kg] = split_x4(xr[j]);
            }
        }
        __syncthreads();
    }

    // ---- final flush ----
    #pragma unroll
    for (int h = 0; h < 2; ++h) {
        const int o0 = cur_tile * TROWS + rowsub + 16 * h;
        #pragma unroll
        for (int t = 0; t < 4; ++t) {
            const int n0 = 8 * t + 2 * q;
            atomicAdd(&out[(size_t)n0 * POUT + o0],           sc * acc[h][t][0]);
            atomicAdd(&out[(size_t)(n0 + 1) * POUT + o0],     sc * acc[h][t][1]);
            atomicAdd(&out[(size_t)n0 * POUT + o0 + 8],       sc * acc[h][t][2]);
            atomicAdd(&out[(size_t)(n0 + 1) * POUT + o0 + 8], sc * acc[h][t][3]);
        }
    }
}

extern "C" void kernel_launch(void* const* d_in, const int* in_sizes, int n_in,
                              void* d_out, int out_size) {
    const float* x = nullptr;
    const float* lut = nullptr;
    const float* bias = nullptr;
    const int*   widx = nullptr;
    for (int i = 0; i < n_in; ++i) {
        if (in_sizes[i] == PB * PIN)            x    = (const float*)d_in[i];
        else if (in_sizes[i] == 256)            lut  = (const float*)d_in[i];
        else if (in_sizes[i] == POUT)           bias = (const float*)d_in[i];
        else                                    widx = (const int*)d_in[i];
    }
    float* out = (float*)d_out;

    cudaFuncSetAttribute(linear_int8_mma_kernel,
                         cudaFuncAttributeMaxDynamicSharedMemorySize, SMEM_BYTES);
    prep_out_kernel<<<4 * PB, 256>>>(x, lut, bias, out);
    linear_int8_mma_kernel<<<NCTA, NTHREADS, SMEM_BYTES>>>(x, lut, bias, widx, out);
}

// round 11
// speedup vs baseline: 2.5816x; 1.0403x over previous
#include <cuda_runtime.h>
#include <cuda_fp16.h>
#include <cstdint>

// ---------------------------------------------------------------------------
// y[b,o] = sum_i x[b,i] * lut[widx[o,i]] + bias[o]
//   B=32, IN=8192, OUT=16384 ; lut affine: lut[c] = lut[0] + c*(lut[1]-lut[0])
//
// Exact-precision fp16 MMA scheme (validated R3..R10):
//   A = (idx-128) exact in fp16 via (0x6400|idx) -> 1024+idx, HSUB2 1152.
//   x = x_hi + x_lo fp16 split; 2x mma.m16n8k16.f16, fp32 accum.
//   out preinit = bias[o] + c0*sumx[b]; GEMM adds sc*acc atomically.
//
// R11: 2 CTAs/SM (16 warps/SM) to close the exposed-latency gap that held
// DRAM at 78%. SMEM refit to 100KB/CTA:
//   * W: k16 grps, 4 slots x 16KB, 64B row stride (conflict-free readback
//     without swizzle: bank = 16*(g&1)+4q+w disjoint per quarter-warp).
//   * x: k128 stages, 2 x 18KB, pitch 36 uint4 (=16 mod 32 words ->
//     conflict-free LDS and STS), 16-reg fp32 prefetch.
// Persistent 148*2 CTAs... grid stays 148? No: grid = 296 handled by same
// static partition over 2048 units. All else (atomic flush, prep, L2::256B
// hint, per-thread cp.async transport) unchanged.
// ---------------------------------------------------------------------------

#define PB       32
#define PIN      8192
#define POUT     16384
#define NTHREADS 256
#define NCTA     296                      // 2 CTAs per SM
#define TROWS    256                      // rows per tile
#define NUNIT    2048                     // 64 tiles * 32 k256-chunks
#define XSTG_U4  1152                     // 32 batch * 36 pitch (uint4)
#define SM_W     36864                    // after 2 x stages (2*18432)
#define WSLOT    16384u                   // k16 grp: 256 rows * 64B
#define SMEM_BYTES (SM_W + 4 * WSLOT)     // 102400 (100KB) -> 2 CTAs/SM

__device__ __forceinline__ uint32_t smem_u32(const void* p) {
    uint32_t a;
    asm("{ .reg .u64 t; cvta.to.shared.u64 t, %1; cvt.u32.u64 %0, t; }" : "=r"(a) : "l"(p));
    return a;
}

__device__ __forceinline__ void cpasync16(uint32_t dst, const void* src) {
    asm volatile("cp.async.cg.shared.global.L2::256B [%0], [%1], 16;"
                 :: "r"(dst), "l"(src) : "memory");
}
#define CP_COMMIT() asm volatile("cp.async.commit_group;" ::: "memory")
#define CP_WAIT(n)  asm volatile("cp.async.wait_group %0;" :: "n"(n) : "memory")

#define LDS128(r0, r1, r2, r3, addr)                                  \
    asm volatile("ld.shared.v4.b32 {%0,%1,%2,%3}, [%4];"              \
                 : "=r"(r0), "=r"(r1), "=r"(r2), "=r"(r3) : "r"(addr))

__device__ __forceinline__ void mma_f16(float* c,
                                        uint32_t a0, uint32_t a1, uint32_t a2, uint32_t a3,
                                        uint32_t b0, uint32_t b1) {
    asm volatile(
        "mma.sync.aligned.m16n8k16.row.col.f32.f16.f16.f32 "
        "{%0,%1,%2,%3}, {%4,%5,%6,%7}, {%8,%9}, {%0,%1,%2,%3};"
        : "+f"(c[0]), "+f"(c[1]), "+f"(c[2]), "+f"(c[3])
        : "r"(a0), "r"(a1), "r"(a2), "r"(a3), "r"(b0), "r"(b1));
}

// two int8 codes -> packed half2 of EXACT (idx-128)
__device__ __forceinline__ uint32_t packA(uint32_t i0, uint32_t i1, uint32_t off2) {
    uint32_t r = 0x64006400u | i0 | (i1 << 16);
    __half2 h = __hsub2(*reinterpret_cast<__half2*>(&r),
                        *reinterpret_cast<const __half2*>(&off2));
    return *reinterpret_cast<uint32_t*>(&h);
}

__device__ __forceinline__ uint4 split_x4(float4 v) {
    __half2 h0 = __floats2half2_rn(v.x, v.y);
    __half2 h1 = __floats2half2_rn(v.z, v.w);
    float2 f0 = __half22float2(h0);
    float2 f1 = __half22float2(h1);
    __half2 l0 = __floats2half2_rn(v.x - f0.x, v.y - f0.y);
    __half2 l1 = __floats2half2_rn(v.z - f1.x, v.w - f1.y);
    uint4 s;
    s.x = *reinterpret_cast<uint32_t*>(&h0);
    s.y = *reinterpret_cast<uint32_t*>(&h1);
    s.z = *reinterpret_cast<uint32_t*>(&l0);
    s.w = *reinterpret_cast<uint32_t*>(&l1);
    return s;
}

// ---- fused prep: out[b, o] = bias[o] + c0*sumx[b] (grid = 4*PB) ----
__global__ void prep_out_kernel(const float* __restrict__ x,
                                const float* __restrict__ lut,
                                const float* __restrict__ bias,
                                float* __restrict__ out) {
    __shared__ float red[8];
    const int b       = blockIdx.x >> 2;
    const int quarter = blockIdx.x & 3;

    const float4* xr = reinterpret_cast<const float4*>(x + (size_t)b * PIN);
    float s = 0.0f;
    #pragma unroll
    for (int j = 0; j < (PIN / 4) / 256; ++j) {
        float4 v = __ldg(xr + threadIdx.x + 256 * j);
        s += (v.x + v.y) + (v.z + v.w);
    }
    #pragma unroll
    for (int o = 16; o; o >>= 1) s += __shfl_xor_sync(0xFFFFFFFFu, s, o);
    if ((threadIdx.x & 31) == 0) red[threadIdx.x >> 5] = s;
    __syncthreads();
    {
        float t = red[0];
        #pragma unroll
        for (int k = 1; k < 8; ++k) t += red[k];
        s = t;                                             // deterministic order
    }

    const float l0 = __ldg(lut);
    const float sc = __ldg(lut + 1) - l0;
    const float c0 = fmaf(128.0f, sc, l0);
    const float addv = c0 * s;

    const int obase = quarter * (POUT / 4);
    const float4* bq = reinterpret_cast<const float4*>(bias + obase);
    float4* oq = reinterpret_cast<float4*>(out + (size_t)b * POUT + obase);
    #pragma unroll
    for (int j = 0; j < (POUT / 4) / 4 / 256; ++j) {
        float4 bv = __ldg(bq + threadIdx.x + 256 * j);
        bv.x += addv; bv.y += addv; bv.z += addv; bv.w += addv;
        oq[threadIdx.x + 256 * j] = bv;
    }
}

__global__ void __launch_bounds__(NTHREADS, 2)
linear_int8_mma_kernel(const float* __restrict__ x,
                       const float* __restrict__ lut,
                       const float* __restrict__ bias,
                       const int*   __restrict__ widx,
                       float*       __restrict__ out) {
    extern __shared__ __align__(16) uint4 xs[];   // x: 2 x 1152 uint4 ; W after
    const uint32_t sbase = smem_u32(xs);

    const int tid  = threadIdx.x;
    const int w    = tid >> 5;
    const int lane = tid & 31;
    const int g    = lane >> 2;       // fragment group: A row / B col
    const int q    = lane & 3;        // fragment k-slot

    const float l0 = __ldg(lut);
    const float sc = __ldg(lut + 1) - l0;
    const uint32_t off1152 = 0x64806480u;   // half2(1152,1152)

    // ---- this CTA's flat k256-chunk range [s, e) ----
    const int s = (int)(((unsigned)blockIdx.x * NUNIT) / NCTA);
    const int e = (int)((((unsigned)blockIdx.x + 1) * NUNIT) / NCTA);
    const int gEnd = e * 16;                   // k16-grp end

    // warp covers rows rowsub + {0,8,16,24} of the 256-row tile
    const int rowsub = w * 32 + g;
    const char* wr0 = reinterpret_cast<const char*>(widx)
                      + (size_t)rowsub * PIN * 4 + (size_t)q * 16;
    const size_t TILESTRIDE = (size_t)TROWS * PIN * 4;    // 8MB per tile
    const size_t J8 = (size_t)8 * PIN * 4;                // +8 rows

    // thread's W smem address (64B row stride, own copies, conflict-free)
    const uint32_t wsl_thr = sbase + SM_W + (uint32_t)rowsub * 64u + (uint32_t)q * 16u;

    float acc[2][4][4];
    #pragma unroll
    for (int h = 0; h < 2; ++h)
        #pragma unroll
        for (int t = 0; t < 4; ++t)
            #pragma unroll
            for (int i = 0; i < 4; ++i) acc[h][t][i] = 0.0f;

    // ---- prologue: issue W k16-grps s*16 .. +3 into slots 0..3 ----
    #pragma unroll
    for (int sidx = 0; sidx < 4; ++sidx) {
        const int gg = s * 16 + sidx;
        const int c0u = gg >> 4;
        const int k16 = (c0u & 31) * 16 + (gg & 15);
        const char* p = wr0 + (size_t)(c0u >> 5) * TILESTRIDE + (size_t)k16 * 64;
        const uint32_t ds = wsl_thr + (uint32_t)(gg & 3) * WSLOT;
        #pragma unroll
        for (int j = 0; j < 4; ++j) cpasync16(ds + (uint32_t)j * 512u, p + (size_t)j * J8);
        CP_COMMIT();
    }

    // ---- stage x: half 0 of unit s ----
    const float4* xg = reinterpret_cast<const float4*>(x);
    float4 xr[4];
    {
        const int kb4 = (s & 31) * 64;
        #pragma unroll
        for (int j = 0; j < 4; ++j)
            xr[j] = __ldg(xg + (size_t)(w + 8 * j) * (PIN / 4) + kb4 + lane);
        uint4* db = xs + ((s * 2) & 1) * XSTG_U4;
        #pragma unroll
        for (int j = 0; j < 4; ++j)
            db[(w + 8 * j) * 36 + lane] = split_x4(xr[j]);
    }
    __syncthreads();

    int cur_tile = s >> 5;

    for (int c = s; c < e; ++c) {
        const int t_tile = c >> 5;
        if (t_tile != cur_tile) {
            #pragma unroll
            for (int h = 0; h < 2; ++h) {
                const int o0 = cur_tile * TROWS + rowsub + 16 * h;
                #pragma unroll
                for (int t = 0; t < 4; ++t) {
                    const int n0 = 8 * t + 2 * q;
                    atomicAdd(&out[(size_t)n0 * POUT + o0],           sc * acc[h][t][0]);
                    atomicAdd(&out[(size_t)(n0 + 1) * POUT + o0],     sc * acc[h][t][1]);
                    atomicAdd(&out[(size_t)n0 * POUT + o0 + 8],       sc * acc[h][t][2]);
                    atomicAdd(&out[(size_t)(n0 + 1) * POUT + o0 + 8], sc * acc[h][t][3]);
                    acc[h][t][0] = acc[h][t][1] = acc[h][t][2] = acc[h][t][3] = 0.0f;
                }
            }
            cur_tile = t_tile;
        }

        #pragma unroll
        for (int h = 0; h < 2; ++h) {
            const uint4* xb = xs + ((c * 2 + h) & 1) * XSTG_U4;

            // prefetch next k128 half of x into registers
            const int nexthalf = c * 2 + h + 1;
            const bool more = nexthalf < e * 2;
            if (more) {
                const int cn = nexthalf >> 1, hn = nexthalf & 1;
                const int kb4 = (cn & 31) * 64 + hn * 32;
                #pragma unroll
                for (int j = 0; j < 4; ++j)
                    xr[j] = __ldg(xg + (size_t)(w + 8 * j) * (PIN / 4) + kb4 + lane);
            }

            const int gbase = c * 16 + h * 8;
            #pragma unroll
            for (int st = 0; st < 8; ++st) {
                const int gg = gbase + st;
                const int rem = gEnd - gg;
                if (rem > 3)       { CP_WAIT(3); }
                else if (rem == 3) { CP_WAIT(2); }
                else if (rem == 2) { CP_WAIT(1); }
                else               { CP_WAIT(0); }

                // ---- W readback: 4 rows x k16 (conflict-free, 64B stride) ----
                const uint32_t rb = wsl_thr + (uint32_t)(gg & 3) * WSLOT;
                uint4 cw[4];
                #pragma unroll
                for (int j = 0; j < 4; ++j)
                    LDS128(cw[j].x, cw[j].y, cw[j].z, cw[j].w, rb + (uint32_t)j * 512u);

                // ---- refill this slot with grp gg+4 ----
                if (gg + 4 < gEnd) {
                    const int gn = gg + 4;
                    const int cnu = gn >> 4;
                    const int k16n = (cnu & 31) * 16 + (gn & 15);
                    const char* p = wr0 + (size_t)(cnu >> 5) * TILESTRIDE + (size_t)k16n * 64;
                    #pragma unroll
                    for (int j = 0; j < 4; ++j)
                        cpasync16(rb + (uint32_t)j * 512u, p + (size_t)j * J8);
                    CP_COMMIT();
                }

                // ---- dequant ----
                const uint32_t A00 = packA(cw[0].x, cw[0].y, off1152);
                const uint32_t A02 = packA(cw[0].z, cw[0].w, off1152);
                const uint32_t A01 = packA(cw[1].x, cw[1].y, off1152);
                const uint32_t A03 = packA(cw[1].z, cw[1].w, off1152);
                const uint32_t A10 = packA(cw[2].x, cw[2].y, off1152);
                const uint32_t A12 = packA(cw[2].z, cw[2].w, off1152);
                const uint32_t A11 = packA(cw[3].x, cw[3].y, off1152);
                const uint32_t A13 = packA(cw[3].z, cw[3].w, off1152);

                // ---- x fragments + MMA (x shared by both m16 tiles) ----
                const int entry = st * 4 + q;
                #pragma unroll
                for (int t = 0; t < 4; ++t) {
                    const uint4 xv = xb[(g + 8 * t) * 36 + entry];
                    mma_f16(acc[0][t], A00, A01, A02, A03, xv.x, xv.y);
                    mma_f16(acc[0][t], A00, A01, A02, A03, xv.z, xv.w);
                    mma_f16(acc[1][t], A10, A11, A12, A13, xv.x, xv.y);
                    mma_f16(acc[1][t], A10, A11, A12, A13, xv.z, xv.w);
                }
            }

            // store prefetched x into the other buffer, then sync
            if (more) {
                uint4* db = xs + (nexthalf & 1) * XSTG_U4;
                #pragma unroll
                for (int j = 0; j < 4; ++j)
                    db[(w + 8 * j) * 36 + lane] = split_x4(xr[j]);
            }
            __syncthreads();
        }
    }

    // ---- final flush ----
    #pragma unroll
    for (int h = 0; h < 2; ++h) {
        const int o0 = cur_tile * TROWS + rowsub + 16 * h;
        #pragma unroll
        for (int t = 0; t < 4; ++t) {
            const int n0 = 8 * t + 2 * q;
            atomicAdd(&out[(size_t)n0 * POUT + o0],           sc * acc[h][t][0]);
            atomicAdd(&out[(size_t)(n0 + 1) * POUT + o0],     sc * acc[h][t][1]);
            atomicAdd(&out[(size_t)n0 * POUT + o0 + 8],       sc * acc[h][t][2]);
            atomicAdd(&out[(size_t)(n0 + 1) * POUT + o0 + 8], sc * acc[h][t][3]);
        }
    }
}

extern "C" void kernel_launch(void* const* d_in, const int* in_sizes, int n_in,
                              void* d_out, int out_size) {
    const float* x = nullptr;
    const float* lut = nullptr;
    const float* bias = nullptr;
    const int*   widx = nullptr;
    for (int i = 0; i < n_in; ++i) {
        if (in_sizes[i] == PB * PIN)            x    = (const float*)d_in[i];
        else if (in_sizes[i] == 256)            lut  = (const float*)d_in[i];
        else if (in_sizes[i] == POUT)           bias = (const float*)d_in[i];
        else                                    widx = (const int*)d_in[i];
    }
    float* out = (float*)d_out;

    cudaFuncSetAttribute(linear_int8_mma_kernel,
                         cudaFuncAttributeMaxDynamicSharedMemorySize, SMEM_BYTES);
    prep_out_kernel<<<4 * PB, 256>>>(x, lut, bias, out);
    linear_int8_mma_kernel<<<NCTA, NTHREADS, SMEM_BYTES>>>(x, lut, bias, widx, out);
}